// round 1
// baseline (speedup 1.0000x reference)
#include <cuda_runtime.h>
#include <cstdint>

#define D        128
#define NMAX     100000
#define CHUNK    64          // rows per GEMM chunk
#define GEMM_THREADS 256

// Scratch: aggregated neighbor features h_n[N][D]
__device__ float g_h[(size_t)NMAX * D];

// ---------------------------------------------------------------------------
// Kernel 0: zero g_h
// ---------------------------------------------------------------------------
__global__ void zero_h_kernel(int n4) {
    float4 z = make_float4(0.f, 0.f, 0.f, 0.f);
    float4* p = reinterpret_cast<float4*>(g_h);
    for (int i = blockIdx.x * blockDim.x + threadIdx.x; i < n4;
         i += gridDim.x * blockDim.x) {
        p[i] = z;
    }
}

// ---------------------------------------------------------------------------
// Kernel 1: edge scatter  h[dst] += e_attn * x[src]
// One warp per edge; each lane handles one float4 (16B); vector red.add.
// ---------------------------------------------------------------------------
__device__ __forceinline__ void red_add_v4(float* addr, float4 v) {
    asm volatile("red.global.add.v4.f32 [%0], {%1, %2, %3, %4};"
                 :: "l"(addr), "f"(v.x), "f"(v.y), "f"(v.z), "f"(v.w)
                 : "memory");
}

__global__ void scatter_kernel(const float* __restrict__ x,
                               const int* __restrict__ src,
                               const int* __restrict__ dst,
                               const float* __restrict__ ea,
                               int E) {
    int gtid = blockIdx.x * blockDim.x + threadIdx.x;
    int e    = gtid >> 5;
    int lane = threadIdx.x & 31;
    if (e >= E) return;

    int   s = __ldg(src + e);
    int   d = __ldg(dst + e);
    float w = __ldg(ea + e);

    const float4* xs = reinterpret_cast<const float4*>(x + (size_t)s * D) + lane;
    float4 v = __ldg(xs);
    v.x *= w; v.y *= w; v.z *= w; v.w *= w;

    red_add_v4(g_h + (size_t)d * D + lane * 4, v);
}

// ---------------------------------------------------------------------------
// Kernel 2: fused bi-interaction GEMM
//   out = lrelu((x+h) @ W1^T + b1) + lrelu((x*h) @ W2^T + b2)
// Persistent blocks. smem: W1^T, W2^T (conflict-free layout [d][o]) +
// staged A = x+h and M = x*h tiles (CHUNK x D).
// Thread tile: 8 rows x 4 cols, two accumulator sets.
// ---------------------------------------------------------------------------
__device__ __forceinline__ float lrelu(float v) {
    return v >= 0.f ? v : 0.01f * v;
}

__global__ __launch_bounds__(GEMM_THREADS, 1)
void gemm_kernel(const float* __restrict__ x,
                 const float* __restrict__ W1,
                 const float* __restrict__ b1,
                 const float* __restrict__ W2,
                 const float* __restrict__ b2,
                 float* __restrict__ out,
                 int n, int nchunks) {
    extern __shared__ float sm[];
    float* sW1 = sm;                     // [D][D] transposed: sW1[d*D + o]
    float* sW2 = sm + D * D;             // [D][D]
    float* sA  = sm + 2 * D * D;         // [CHUNK][D]
    float* sM  = sA + CHUNK * D;         // [CHUNK][D]

    const int tid  = threadIdx.x;
    const int colt = tid & 31;           // 32 column groups
    const int rowt = tid >> 5;           // 8 row groups
    const int c0   = colt * 4;           // first of 4 output cols

    // Load W transposed into smem (one-time; conflicts here are negligible)
    for (int i = tid; i < D * D; i += GEMM_THREADS) {
        int o = i >> 7, d = i & (D - 1);
        sW1[d * D + o] = W1[i];
        sW2[d * D + o] = W2[i];
    }

    float b1a[4], b2a[4];
    {
        float4 t1 = *reinterpret_cast<const float4*>(b1 + c0);
        float4 t2 = *reinterpret_cast<const float4*>(b2 + c0);
        b1a[0]=t1.x; b1a[1]=t1.y; b1a[2]=t1.z; b1a[3]=t1.w;
        b2a[0]=t2.x; b2a[1]=t2.y; b2a[2]=t2.z; b2a[3]=t2.w;
    }

    for (int chunk = blockIdx.x; chunk < nchunks; chunk += gridDim.x) {
        const int row0 = chunk * CHUNK;

        __syncthreads();   // protect sA/sM of previous chunk (and W on iter 0)

        // Stage A = x+h, M = x*h for CHUNK rows (float4 per thread-iter)
        for (int i = tid; i < CHUNK * D / 4; i += GEMM_THREADS) {
            int r  = i >> 5;            // row within chunk (D/4 = 32 f4/row)
            int dd = (i & 31) * 4;
            int grow = row0 + r;
            float4 xv, hv;
            if (grow < n) {
                xv = *reinterpret_cast<const float4*>(x   + (size_t)grow * D + dd);
                hv = *reinterpret_cast<const float4*>(g_h + (size_t)grow * D + dd);
            } else {
                xv = make_float4(0.f,0.f,0.f,0.f);
                hv = xv;
            }
            float4 av = make_float4(xv.x+hv.x, xv.y+hv.y, xv.z+hv.z, xv.w+hv.w);
            float4 mv = make_float4(xv.x*hv.x, xv.y*hv.y, xv.z*hv.z, xv.w*hv.w);
            *reinterpret_cast<float4*>(sA + r * D + dd) = av;
            *reinterpret_cast<float4*>(sM + r * D + dd) = mv;
        }
        __syncthreads();

        float acc1[8][4], acc2[8][4];
        #pragma unroll
        for (int r = 0; r < 8; ++r)
            #pragma unroll
            for (int c = 0; c < 4; ++c) { acc1[r][c] = 0.f; acc2[r][c] = 0.f; }

        #pragma unroll 4
        for (int dd = 0; dd < D; dd += 4) {
            float4 w1q[4], w2q[4];
            #pragma unroll
            for (int j = 0; j < 4; ++j) {
                w1q[j] = *reinterpret_cast<const float4*>(sW1 + (dd + j) * D + c0);
                w2q[j] = *reinterpret_cast<const float4*>(sW2 + (dd + j) * D + c0);
            }
            #pragma unroll
            for (int r = 0; r < 8; ++r) {
                float4 av = *reinterpret_cast<const float4*>(sA + (rowt*8 + r) * D + dd);
                float4 mv = *reinterpret_cast<const float4*>(sM + (rowt*8 + r) * D + dd);
                float a4[4] = {av.x, av.y, av.z, av.w};
                float m4[4] = {mv.x, mv.y, mv.z, mv.w};
                #pragma unroll
                for (int j = 0; j < 4; ++j) {
                    const float* w1f = reinterpret_cast<const float*>(&w1q[j]);
                    const float* w2f = reinterpret_cast<const float*>(&w2q[j]);
                    #pragma unroll
                    for (int c = 0; c < 4; ++c) {
                        acc1[r][c] += a4[j] * w1f[c];
                        acc2[r][c] += m4[j] * w2f[c];
                    }
                }
            }
        }

        // Epilogue: bias + leaky relu + sum, vectorized store
        #pragma unroll
        for (int r = 0; r < 8; ++r) {
            int grow = row0 + rowt * 8 + r;
            if (grow < n) {
                float4 o;
                o.x = lrelu(acc1[r][0] + b1a[0]) + lrelu(acc2[r][0] + b2a[0]);
                o.y = lrelu(acc1[r][1] + b1a[1]) + lrelu(acc2[r][1] + b2a[1]);
                o.z = lrelu(acc1[r][2] + b1a[2]) + lrelu(acc2[r][2] + b2a[2]);
                o.w = lrelu(acc1[r][3] + b1a[3]) + lrelu(acc2[r][3] + b2a[3]);
                *reinterpret_cast<float4*>(out + (size_t)grow * D + c0) = o;
            }
        }
    }
}

// ---------------------------------------------------------------------------
// Launch
// Inputs (metadata order): x[N*128] f32, src[E] i32, dst[E] i32, e_attn[E] f32,
//                          W1[128*128] f32, b1[128] f32, W2[128*128] f32, b2[128] f32
// Output: [N*128] f32
// ---------------------------------------------------------------------------
extern "C" void kernel_launch(void* const* d_in, const int* in_sizes, int n_in,
                              void* d_out, int out_size) {
    const float* x   = (const float*)d_in[0];
    const int*   src = (const int*)  d_in[1];
    const int*   dst = (const int*)  d_in[2];
    const float* ea  = (const float*)d_in[3];
    const float* W1  = (const float*)d_in[4];
    const float* b1  = (const float*)d_in[5];
    const float* W2  = (const float*)d_in[6];
    const float* b2  = (const float*)d_in[7];
    float*       out = (float*)d_out;

    const int n = in_sizes[0] / D;
    const int E = in_sizes[1];

    // 0) zero h
    {
        int n4 = n * D / 4;
        zero_h_kernel<<<2048, 256>>>(n4);
    }

    // 1) scatter: one warp per edge
    {
        int warps_per_block = 8;
        int blocks = (E + warps_per_block - 1) / warps_per_block;
        scatter_kernel<<<blocks, warps_per_block * 32>>>(x, src, dst, ea, E);
    }

    // 2) fused GEMM + epilogue, persistent blocks
    {
        const int smem_bytes = (2 * D * D + 2 * CHUNK * D) * (int)sizeof(float); // 192KB
        static_assert((2 * D * D + 2 * CHUNK * D) * sizeof(float) == 196608, "smem size");
        cudaFuncSetAttribute(gemm_kernel,
                             cudaFuncAttributeMaxDynamicSharedMemorySize, smem_bytes);
        int nchunks = (n + CHUNK - 1) / CHUNK;
        gemm_kernel<<<152, GEMM_THREADS, smem_bytes>>>(x, W1, b1, W2, b2, out, n, nchunks);
    }
}

// round 6
// speedup vs baseline: 1.1600x; 1.1600x over previous
#include <cuda_runtime.h>
#include <cuda_fp16.h>
#include <cstdint>

#define D        128
#define NMAX     100000
#define EMAX     1600000
#define TILE_M   128
#define GT       256     // gemm threads (8 warps)

// ---------------------------------------------------------------------------
// Device scratch
// ---------------------------------------------------------------------------
__device__ float g_h[(size_t)NMAX * D];   // aggregated neighbor features
__device__ int   g_cnt[NMAX];
__device__ int   g_off[NMAX + 1];
__device__ int   g_cur[NMAX];
__device__ int2  g_epk[EMAX];             // packed {src, bits(e_attn)} sorted by dst

// ---------------------------------------------------------------------------
// CSR build: zero counts -> histogram -> scan -> fill
// ---------------------------------------------------------------------------
__global__ void zero_cnt_kernel(int n) {
    for (int i = blockIdx.x * blockDim.x + threadIdx.x; i < n;
         i += gridDim.x * blockDim.x)
        g_cnt[i] = 0;
}

__global__ void hist_kernel(const int* __restrict__ dst, int E) {
    int e = blockIdx.x * blockDim.x + threadIdx.x;
    if (e < E) atomicAdd(&g_cnt[dst[e]], 1);
}

__global__ void scan_kernel(int n) {
    __shared__ int sh[1024];
    int tid = threadIdx.x;
    int chunk = (n + 1023) >> 10;
    int lo = tid * chunk;
    int hi = lo + chunk; if (hi > n) hi = n;
    int s = 0;
    for (int i = lo; i < hi; ++i) s += g_cnt[i];
    sh[tid] = s;
    __syncthreads();
    for (int d = 1; d < 1024; d <<= 1) {
        int t = (tid >= d) ? sh[tid - d] : 0;
        __syncthreads();
        sh[tid] += t;
        __syncthreads();
    }
    int run = sh[tid] - s;      // exclusive prefix of this thread's chunk
    for (int i = lo; i < hi; ++i) {
        int c = g_cnt[i];
        g_off[i] = run;
        g_cur[i] = run;
        run += c;
    }
    if (tid == 1023) g_off[n] = sh[1023];
}

__global__ void fill_kernel(const int* __restrict__ src, const int* __restrict__ dst,
                            const float* __restrict__ ea, int E) {
    int e = blockIdx.x * blockDim.x + threadIdx.x;
    if (e < E) {
        int d = dst[e];
        int p = atomicAdd(&g_cur[d], 1);
        g_epk[p] = make_int2(src[e], __float_as_int(ea[e]));
    }
}

// ---------------------------------------------------------------------------
// Gather: one warp per node, atomic-free accumulation, writes h once.
// ---------------------------------------------------------------------------
__global__ void gather_kernel(const float* __restrict__ x, int n) {
    int w = (blockIdx.x * blockDim.x + threadIdx.x) >> 5;
    if (w >= n) return;
    int lane = threadIdx.x & 31;
    int j   = g_off[w];
    int end = g_off[w + 1];
    const float4* xb = reinterpret_cast<const float4*>(x);
    float4 acc = make_float4(0.f, 0.f, 0.f, 0.f);
    for (; j + 2 <= end; j += 2) {
        int2 p0 = g_epk[j];
        int2 p1 = g_epk[j + 1];
        float4 v0 = __ldg(xb + (size_t)p0.x * 32 + lane);
        float4 v1 = __ldg(xb + (size_t)p1.x * 32 + lane);
        float w0 = __int_as_float(p0.y), w1 = __int_as_float(p1.y);
        acc.x = fmaf(w0, v0.x, acc.x); acc.y = fmaf(w0, v0.y, acc.y);
        acc.z = fmaf(w0, v0.z, acc.z); acc.w = fmaf(w0, v0.w, acc.w);
        acc.x = fmaf(w1, v1.x, acc.x); acc.y = fmaf(w1, v1.y, acc.y);
        acc.z = fmaf(w1, v1.z, acc.z); acc.w = fmaf(w1, v1.w, acc.w);
    }
    if (j < end) {
        int2 p0 = g_epk[j];
        float4 v0 = __ldg(xb + (size_t)p0.x * 32 + lane);
        float w0 = __int_as_float(p0.y);
        acc.x = fmaf(w0, v0.x, acc.x); acc.y = fmaf(w0, v0.y, acc.y);
        acc.z = fmaf(w0, v0.z, acc.z); acc.w = fmaf(w0, v0.w, acc.w);
    }
    reinterpret_cast<float4*>(g_h)[(size_t)w * 32 + lane] = acc;
}

// ---------------------------------------------------------------------------
// HMMA GEMM: out = lrelu((x+h)@W1^T + b1) + lrelu((x*h)@W2^T + b2)
// fp16 operands, fp32 accumulation via mma.sync.m16n8k16.
// Persistent CTAs; CTA tile 128x128, warp tile 32x64, 8 warps.
// ---------------------------------------------------------------------------
// smem byte offsets (halves, 256B rows, XOR-swizzled 16B chunks)
#define SM_W1   0
#define SM_W2   32768
#define SM_A    65536
#define SM_MU   98304
#define SM_B1   131072
#define SM_B2   131584
#define SM_TOT  132096

// swizzle: row-major 128x128 halves; permute 16B chunks by row to make
// 8-consecutive-row ldmatrix accesses conflict-free.
__device__ __forceinline__ uint32_t swz(int row, int kb) {
    return (uint32_t)(row * 256 + (kb ^ ((row & 7) << 4)));
}

__device__ __forceinline__ uint32_t pack_h2(float a, float b) {
    __half2 h = __float22half2_rn(make_float2(a, b));
    return *reinterpret_cast<uint32_t*>(&h);
}

__device__ __forceinline__ float lrelu(float v) {
    return v >= 0.f ? v : 0.01f * v;
}

__device__ __forceinline__ void ldsm_x4(uint32_t* r, uint32_t addr) {
    asm volatile("ldmatrix.sync.aligned.m8n8.x4.shared.b16 {%0,%1,%2,%3}, [%4];"
                 : "=r"(r[0]), "=r"(r[1]), "=r"(r[2]), "=r"(r[3]) : "r"(addr));
}
__device__ __forceinline__ void ldsm_x2(uint32_t* r, uint32_t addr) {
    asm volatile("ldmatrix.sync.aligned.m8n8.x2.shared.b16 {%0,%1}, [%2];"
                 : "=r"(r[0]), "=r"(r[1]) : "r"(addr));
}
__device__ __forceinline__ void mma16816(float* c, const uint32_t* a, const uint32_t* b) {
    asm volatile(
        "mma.sync.aligned.m16n8k16.row.col.f32.f16.f16.f32 "
        "{%0,%1,%2,%3}, {%4,%5,%6,%7}, {%8,%9}, {%0,%1,%2,%3};"
        : "+f"(c[0]), "+f"(c[1]), "+f"(c[2]), "+f"(c[3])
        : "r"(a[0]), "r"(a[1]), "r"(a[2]), "r"(a[3]), "r"(b[0]), "r"(b[1]));
}

__global__ __launch_bounds__(GT, 1)
void gemm_kernel(const float* __restrict__ x,
                 const float* __restrict__ W1, const float* __restrict__ b1,
                 const float* __restrict__ W2, const float* __restrict__ b2,
                 float* __restrict__ out, int n, int ntiles) {
    extern __shared__ char smem[];
    uint32_t sb = (uint32_t)__cvta_generic_to_shared(smem);
    const int tid  = threadIdx.x;
    const int wid  = tid >> 5;
    const int lane = tid & 31;
    const int wm   = wid >> 1;          // 0..3 -> mbase = wm*32
    const int wn   = wid & 1;           // 0..1 -> nbase = wn*64
    const int mbase = wm * 32;
    const int nbase = wn * 64;

    // Stage W1, W2 as fp16 (swizzled), biases as f32
    for (int i = tid; i < D * D / 8; i += GT) {       // 2048 chunks of 8 halves
        int row = i >> 4;
        int k0  = (i & 15) << 3;
        const float* w1p = W1 + row * D + k0;
        const float* w2p = W2 + row * D + k0;
        float4 a0 = *reinterpret_cast<const float4*>(w1p);
        float4 a1 = *reinterpret_cast<const float4*>(w1p + 4);
        float4 c0 = *reinterpret_cast<const float4*>(w2p);
        float4 c1 = *reinterpret_cast<const float4*>(w2p + 4);
        uint4 u1, u2;
        u1.x = pack_h2(a0.x, a0.y); u1.y = pack_h2(a0.z, a0.w);
        u1.z = pack_h2(a1.x, a1.y); u1.w = pack_h2(a1.z, a1.w);
        u2.x = pack_h2(c0.x, c0.y); u2.y = pack_h2(c0.z, c0.w);
        u2.z = pack_h2(c1.x, c1.y); u2.w = pack_h2(c1.z, c1.w);
        uint32_t off = swz(row, k0 * 2);
        *reinterpret_cast<uint4*>(smem + SM_W1 + off) = u1;
        *reinterpret_cast<uint4*>(smem + SM_W2 + off) = u2;
    }
    if (tid < D) {
        *reinterpret_cast<float*>(smem + SM_B1 + tid * 4) = b1[tid];
        *reinterpret_cast<float*>(smem + SM_B2 + tid * 4) = b2[tid];
    }
    __syncthreads();

    for (int tile = blockIdx.x; tile < ntiles; tile += gridDim.x) {
        const int row0 = tile * TILE_M;

        // Stage A = fp16(x+h), MU = fp16(x*h), swizzled
        for (int i = tid; i < TILE_M * 16; i += GT) {
            int r  = i >> 4;
            int k0 = (i & 15) << 3;
            int grow = row0 + r;
            uint4 ua, um;
            if (grow < n) {
                const float* xp = x   + (size_t)grow * D + k0;
                const float* hp = g_h + (size_t)grow * D + k0;
                float4 x0 = *reinterpret_cast<const float4*>(xp);
                float4 x1 = *reinterpret_cast<const float4*>(xp + 4);
                float4 h0 = *reinterpret_cast<const float4*>(hp);
                float4 h1 = *reinterpret_cast<const float4*>(hp + 4);
                ua.x = pack_h2(x0.x + h0.x, x0.y + h0.y);
                ua.y = pack_h2(x0.z + h0.z, x0.w + h0.w);
                ua.z = pack_h2(x1.x + h1.x, x1.y + h1.y);
                ua.w = pack_h2(x1.z + h1.z, x1.w + h1.w);
                um.x = pack_h2(x0.x * h0.x, x0.y * h0.y);
                um.y = pack_h2(x0.z * h0.z, x0.w * h0.w);
                um.z = pack_h2(x1.x * h1.x, x1.y * h1.y);
                um.w = pack_h2(x1.z * h1.z, x1.w * h1.w);
            } else {
                ua = make_uint4(0, 0, 0, 0);
                um = ua;
            }
            uint32_t off = swz(r, k0 * 2);
            *reinterpret_cast<uint4*>(smem + SM_A  + off) = ua;
            *reinterpret_cast<uint4*>(smem + SM_MU + off) = um;
        }
        __syncthreads();

        float c1[2][8][4], c2[2][8][4];
        #pragma unroll
        for (int i = 0; i < 2; ++i)
            #pragma unroll
            for (int j = 0; j < 8; ++j)
                #pragma unroll
                for (int q = 0; q < 4; ++q) { c1[i][j][q] = 0.f; c2[i][j][q] = 0.f; }

        for (int ks = 0; ks < 8; ++ks) {
            const int kb0 = ks * 32;                 // byte offset of k-chunk
            // A fragments (x4): row = mbase+i*16+(lane&15), kb = kb0 + (lane>>4)*16
            uint32_t aA[2][4], aM[2][4];
            #pragma unroll
            for (int i = 0; i < 2; ++i) {
                uint32_t off = swz(mbase + i * 16 + (lane & 15), kb0 + ((lane >> 4) << 4));
                ldsm_x4(aA[i], sb + SM_A  + off);
                ldsm_x4(aM[i], sb + SM_MU + off);
            }
            #pragma unroll
            for (int j = 0; j < 8; ++j) {
                // B fragments (x2): row = nbase+j*8+(lane&7), kb = kb0 + ((lane>>3)&1)*16
                uint32_t boff = swz(nbase + j * 8 + (lane & 7), kb0 + (((lane >> 3) & 1) << 4));
                uint32_t bW1[2], bW2[2];
                ldsm_x2(bW1, sb + SM_W1 + boff);
                ldsm_x2(bW2, sb + SM_W2 + boff);
                #pragma unroll
                for (int i = 0; i < 2; ++i) {
                    mma16816(c1[i][j], aA[i], bW1);
                    mma16816(c2[i][j], aM[i], bW2);
                }
            }
        }

        // Epilogue: bias + leaky relu + sum; c frag rows: t/4 and t/4+8
        const int rbase = row0 + mbase + (lane >> 2);
        #pragma unroll
        for (int j = 0; j < 8; ++j) {
            int col = nbase + j * 8 + 2 * (lane & 3);
            float2 bb1 = *reinterpret_cast<const float2*>(smem + SM_B1 + col * 4);
            float2 bb2 = *reinterpret_cast<const float2*>(smem + SM_B2 + col * 4);
            #pragma unroll
            for (int i = 0; i < 2; ++i) {
                int r0 = rbase + i * 16;
                if (r0 < n) {
                    float2 o;
                    o.x = lrelu(c1[i][j][0] + bb1.x) + lrelu(c2[i][j][0] + bb2.x);
                    o.y = lrelu(c1[i][j][1] + bb1.y) + lrelu(c2[i][j][1] + bb2.y);
                    *reinterpret_cast<float2*>(out + (size_t)r0 * D + col) = o;
                }
                int r1 = r0 + 8;
                if (r1 < n) {
                    float2 o;
                    o.x = lrelu(c1[i][j][2] + bb1.x) + lrelu(c2[i][j][2] + bb2.x);
                    o.y = lrelu(c1[i][j][3] + bb1.y) + lrelu(c2[i][j][3] + bb2.y);
                    *reinterpret_cast<float2*>(out + (size_t)r1 * D + col) = o;
                }
            }
        }
        __syncthreads();
    }
}

// ---------------------------------------------------------------------------
// Launch
// Inputs: x[N*128] f32, src[E] i32, dst[E] i32, e_attn[E] f32,
//         W1[128*128] f32, b1[128] f32, W2[128*128] f32, b2[128] f32
// ---------------------------------------------------------------------------
extern "C" void kernel_launch(void* const* d_in, const int* in_sizes, int n_in,
                              void* d_out, int out_size) {
    const float* x   = (const float*)d_in[0];
    const int*   src = (const int*)  d_in[1];
    const int*   dst = (const int*)  d_in[2];
    const float* ea  = (const float*)d_in[3];
    const float* W1  = (const float*)d_in[4];
    const float* b1  = (const float*)d_in[5];
    const float* W2  = (const float*)d_in[6];
    const float* b2  = (const float*)d_in[7];
    float*       out = (float*)d_out;

    const int n = in_sizes[0] / D;
    const int E = in_sizes[1];

    zero_cnt_kernel<<<256, 256>>>(n);
    hist_kernel<<<(E + 255) / 256, 256>>>(dst, E);
    scan_kernel<<<1, 1024>>>(n);
    fill_kernel<<<(E + 255) / 256, 256>>>(src, dst, ea, E);
    gather_kernel<<<(n + 7) / 8, 256>>>(x, n);

    cudaFuncSetAttribute(gemm_kernel,
                         cudaFuncAttributeMaxDynamicSharedMemorySize, SM_TOT);
    const int ntiles = (n + TILE_M - 1) / TILE_M;
    gemm_kernel<<<148, GT, SM_TOT>>>(x, W1, b1, W2, b2, out, n, ntiles);
}

// round 7
// speedup vs baseline: 2.2087x; 1.9041x over previous
#include <cuda_runtime.h>
#include <cuda_fp16.h>
#include <cstdint>

#define D        128
#define NMAX     100000
#define EMAX     1600000
#define TILE_M   128
#define GT       256     // gemm threads (8 warps)

// ---------------------------------------------------------------------------
// Device scratch
// ---------------------------------------------------------------------------
__device__ float  g_h[(size_t)NMAX * D];    // aggregated neighbor features (fp32)
__device__ __half g_xh[(size_t)NMAX * D];   // fp16 copy of x
__device__ int    g_cnt[NMAX];
__device__ int    g_off[NMAX + 1];
__device__ int    g_cur[NMAX];
__device__ int    g_bsum[256];
__device__ int2   g_epk[EMAX];              // packed {src, bits(e_attn)} sorted by dst

// ---------------------------------------------------------------------------
// x -> fp16 copy
// ---------------------------------------------------------------------------
__global__ void convert_x_kernel(const float* __restrict__ x, int n8) {
    for (int i = blockIdx.x * blockDim.x + threadIdx.x; i < n8;
         i += gridDim.x * blockDim.x) {
        const float* xp = x + (size_t)i * 8;
        float4 a = *reinterpret_cast<const float4*>(xp);
        float4 b = *reinterpret_cast<const float4*>(xp + 4);
        uint4 u;
        __half2 h;
        h = __float22half2_rn(make_float2(a.x, a.y)); u.x = *reinterpret_cast<uint32_t*>(&h);
        h = __float22half2_rn(make_float2(a.z, a.w)); u.y = *reinterpret_cast<uint32_t*>(&h);
        h = __float22half2_rn(make_float2(b.x, b.y)); u.z = *reinterpret_cast<uint32_t*>(&h);
        h = __float22half2_rn(make_float2(b.z, b.w)); u.w = *reinterpret_cast<uint32_t*>(&h);
        *reinterpret_cast<uint4*>(g_xh + (size_t)i * 8) = u;
    }
}

// ---------------------------------------------------------------------------
// CSR build: zero counts -> histogram -> 3-phase scan -> fill
// ---------------------------------------------------------------------------
__global__ void zero_cnt_kernel(int n) {
    for (int i = blockIdx.x * blockDim.x + threadIdx.x; i < n;
         i += gridDim.x * blockDim.x)
        g_cnt[i] = 0;
}

__global__ void hist_kernel(const int* __restrict__ dst, int E) {
    int e = blockIdx.x * blockDim.x + threadIdx.x;
    if (e < E) atomicAdd(&g_cnt[dst[e]], 1);
}

__global__ void bsum_kernel(int n) {
    __shared__ int sh[256];
    int chunk = (n + 255) >> 8;
    int lo = blockIdx.x * chunk;
    int hi = lo + chunk; if (hi > n) hi = n;
    int s = 0;
    for (int i = lo + threadIdx.x; i < hi; i += 256) s += g_cnt[i];
    sh[threadIdx.x] = s;
    __syncthreads();
    for (int d = 128; d; d >>= 1) {
        if (threadIdx.x < d) sh[threadIdx.x] += sh[threadIdx.x + d];
        __syncthreads();
    }
    if (threadIdx.x == 0) g_bsum[blockIdx.x] = sh[0];
}

__global__ void bscan_kernel(int n) {
    __shared__ int sh[256];
    int v = g_bsum[threadIdx.x];
    sh[threadIdx.x] = v;
    __syncthreads();
    for (int d = 1; d < 256; d <<= 1) {
        int t = (threadIdx.x >= d) ? sh[threadIdx.x - d] : 0;
        __syncthreads();
        sh[threadIdx.x] += t;
        __syncthreads();
    }
    g_bsum[threadIdx.x] = sh[threadIdx.x] - v;   // exclusive
    if (threadIdx.x == 255) g_off[n] = sh[255];
}

__global__ void offwrite_kernel(int n) {
    __shared__ int sh[256];
    int chunk = (n + 255) >> 8;
    int lo = blockIdx.x * chunk;
    int hi = lo + chunk; if (hi > n) hi = n;
    int sub = (chunk + 255) >> 8;
    int tlo = lo + threadIdx.x * sub;
    int thi = tlo + sub; if (thi > hi) thi = hi;
    int s = 0;
    for (int i = tlo; i < thi; ++i) s += g_cnt[i];
    sh[threadIdx.x] = s;
    __syncthreads();
    for (int d = 1; d < 256; d <<= 1) {
        int t = (threadIdx.x >= d) ? sh[threadIdx.x - d] : 0;
        __syncthreads();
        sh[threadIdx.x] += t;
        __syncthreads();
    }
    int run = g_bsum[blockIdx.x] + sh[threadIdx.x] - s;
    for (int i = tlo; i < thi; ++i) {
        int c = g_cnt[i];
        g_off[i] = run;
        g_cur[i] = run;
        run += c;
    }
}

__global__ void fill_kernel(const int* __restrict__ src, const int* __restrict__ dst,
                            const float* __restrict__ ea, int E) {
    int e = blockIdx.x * blockDim.x + threadIdx.x;
    if (e < E) {
        int d = dst[e];
        int p = atomicAdd(&g_cur[d], 1);
        g_epk[p] = make_int2(src[e], __float_as_int(ea[e]));
    }
}

// ---------------------------------------------------------------------------
// Gather: one warp per node, fp16 source rows (256B/edge), fp32 accumulation.
// Each lane covers 4 feature dims (uint2 = 4 halves).
// ---------------------------------------------------------------------------
__global__ void gather_kernel(int n) {
    int w = (blockIdx.x * blockDim.x + threadIdx.x) >> 5;
    if (w >= n) return;
    int lane = threadIdx.x & 31;
    int j   = g_off[w];
    int end = g_off[w + 1];
    const uint2* xb = reinterpret_cast<const uint2*>(g_xh);
    float4 acc = make_float4(0.f, 0.f, 0.f, 0.f);

    #pragma unroll 1
    for (; j + 2 <= end; j += 2) {
        int2 p0 = g_epk[j];
        int2 p1 = g_epk[j + 1];
        uint2 v0 = __ldg(xb + (size_t)p0.x * 32 + lane);
        uint2 v1 = __ldg(xb + (size_t)p1.x * 32 + lane);
        float w0 = __int_as_float(p0.y), w1 = __int_as_float(p1.y);
        float2 a0 = __half22float2(*reinterpret_cast<__half2*>(&v0.x));
        float2 a1 = __half22float2(*reinterpret_cast<__half2*>(&v0.y));
        float2 b0 = __half22float2(*reinterpret_cast<__half2*>(&v1.x));
        float2 b1 = __half22float2(*reinterpret_cast<__half2*>(&v1.y));
        acc.x = fmaf(w0, a0.x, acc.x); acc.y = fmaf(w0, a0.y, acc.y);
        acc.z = fmaf(w0, a1.x, acc.z); acc.w = fmaf(w0, a1.y, acc.w);
        acc.x = fmaf(w1, b0.x, acc.x); acc.y = fmaf(w1, b0.y, acc.y);
        acc.z = fmaf(w1, b1.x, acc.z); acc.w = fmaf(w1, b1.y, acc.w);
    }
    if (j < end) {
        int2 p0 = g_epk[j];
        uint2 v0 = __ldg(xb + (size_t)p0.x * 32 + lane);
        float w0 = __int_as_float(p0.y);
        float2 a0 = __half22float2(*reinterpret_cast<__half2*>(&v0.x));
        float2 a1 = __half22float2(*reinterpret_cast<__half2*>(&v0.y));
        acc.x = fmaf(w0, a0.x, acc.x); acc.y = fmaf(w0, a0.y, acc.y);
        acc.z = fmaf(w0, a1.x, acc.z); acc.w = fmaf(w0, a1.y, acc.w);
    }
    reinterpret_cast<float4*>(g_h)[(size_t)w * 32 + lane] = acc;
}

// ---------------------------------------------------------------------------
// HMMA GEMM: out = lrelu((x+h)@W1^T + b1) + lrelu((x*h)@W2^T + b2)
// fp16 operands, fp32 accumulation via mma.sync.m16n8k16.
// Persistent CTAs; CTA tile 128x128, warp tile 32x64, 8 warps.
// ---------------------------------------------------------------------------
#define SM_W1   0
#define SM_W2   32768
#define SM_A    65536
#define SM_MU   98304
#define SM_B1   131072
#define SM_B2   131584
#define SM_TOT  132096

__device__ __forceinline__ uint32_t swz(int row, int kb) {
    return (uint32_t)(row * 256 + (kb ^ ((row & 7) << 4)));
}

__device__ __forceinline__ uint32_t pack_h2(float a, float b) {
    __half2 h = __float22half2_rn(make_float2(a, b));
    return *reinterpret_cast<uint32_t*>(&h);
}

__device__ __forceinline__ float lrelu(float v) {
    return v >= 0.f ? v : 0.01f * v;
}

__device__ __forceinline__ void ldsm_x4(uint32_t* r, uint32_t addr) {
    asm volatile("ldmatrix.sync.aligned.m8n8.x4.shared.b16 {%0,%1,%2,%3}, [%4];"
                 : "=r"(r[0]), "=r"(r[1]), "=r"(r[2]), "=r"(r[3]) : "r"(addr));
}
__device__ __forceinline__ void ldsm_x2(uint32_t* r, uint32_t addr) {
    asm volatile("ldmatrix.sync.aligned.m8n8.x2.shared.b16 {%0,%1}, [%2];"
                 : "=r"(r[0]), "=r"(r[1]) : "r"(addr));
}
__device__ __forceinline__ void mma16816(float* c, const uint32_t* a, const uint32_t* b) {
    asm volatile(
        "mma.sync.aligned.m16n8k16.row.col.f32.f16.f16.f32 "
        "{%0,%1,%2,%3}, {%4,%5,%6,%7}, {%8,%9}, {%0,%1,%2,%3};"
        : "+f"(c[0]), "+f"(c[1]), "+f"(c[2]), "+f"(c[3])
        : "r"(a[0]), "r"(a[1]), "r"(a[2]), "r"(a[3]), "r"(b[0]), "r"(b[1]));
}

__global__ __launch_bounds__(GT, 1)
void gemm_kernel(const float* __restrict__ W1, const float* __restrict__ b1,
                 const float* __restrict__ W2, const float* __restrict__ b2,
                 float* __restrict__ out, int n, int ntiles) {
    extern __shared__ char smem[];
    uint32_t sb = (uint32_t)__cvta_generic_to_shared(smem);
    const int tid  = threadIdx.x;
    const int wid  = tid >> 5;
    const int lane = tid & 31;
    const int mbase = (wid >> 1) * 32;
    const int nbase = (wid & 1) * 64;

    // Stage W1, W2 as fp16 (swizzled), biases as f32
    for (int i = tid; i < D * D / 8; i += GT) {
        int row = i >> 4;
        int k0  = (i & 15) << 3;
        const float* w1p = W1 + row * D + k0;
        const float* w2p = W2 + row * D + k0;
        float4 a0 = *reinterpret_cast<const float4*>(w1p);
        float4 a1 = *reinterpret_cast<const float4*>(w1p + 4);
        float4 c0 = *reinterpret_cast<const float4*>(w2p);
        float4 c1 = *reinterpret_cast<const float4*>(w2p + 4);
        uint4 u1, u2;
        u1.x = pack_h2(a0.x, a0.y); u1.y = pack_h2(a0.z, a0.w);
        u1.z = pack_h2(a1.x, a1.y); u1.w = pack_h2(a1.z, a1.w);
        u2.x = pack_h2(c0.x, c0.y); u2.y = pack_h2(c0.z, c0.w);
        u2.z = pack_h2(c1.x, c1.y); u2.w = pack_h2(c1.z, c1.w);
        uint32_t off = swz(row, k0 * 2);
        *reinterpret_cast<uint4*>(smem + SM_W1 + off) = u1;
        *reinterpret_cast<uint4*>(smem + SM_W2 + off) = u2;
    }
    if (tid < D) {
        *reinterpret_cast<float*>(smem + SM_B1 + tid * 4) = b1[tid];
        *reinterpret_cast<float*>(smem + SM_B2 + tid * 4) = b2[tid];
    }
    __syncthreads();

    for (int tile = blockIdx.x; tile < ntiles; tile += gridDim.x) {
        const int row0 = tile * TILE_M;

        // Stage A = fp16(x+h), MU = fp16(x*h); x from fp16 copy, h fp32
        for (int i = tid; i < TILE_M * 16; i += GT) {
            int r  = i >> 4;
            int k0 = (i & 15) << 3;
            int grow = row0 + r;
            uint4 ua, um;
            if (grow < n) {
                uint4 xv = *reinterpret_cast<const uint4*>(g_xh + (size_t)grow * D + k0);
                const float* hp = g_h + (size_t)grow * D + k0;
                float4 h0 = *reinterpret_cast<const float4*>(hp);
                float4 h1 = *reinterpret_cast<const float4*>(hp + 4);
                float2 x0 = __half22float2(*reinterpret_cast<__half2*>(&xv.x));
                float2 x1 = __half22float2(*reinterpret_cast<__half2*>(&xv.y));
                float2 x2 = __half22float2(*reinterpret_cast<__half2*>(&xv.z));
                float2 x3 = __half22float2(*reinterpret_cast<__half2*>(&xv.w));
                ua.x = pack_h2(x0.x + h0.x, x0.y + h0.y);
                ua.y = pack_h2(x1.x + h0.z, x1.y + h0.w);
                ua.z = pack_h2(x2.x + h1.x, x2.y + h1.y);
                ua.w = pack_h2(x3.x + h1.z, x3.y + h1.w);
                um.x = pack_h2(x0.x * h0.x, x0.y * h0.y);
                um.y = pack_h2(x1.x * h0.z, x1.y * h0.w);
                um.z = pack_h2(x2.x * h1.x, x2.y * h1.y);
                um.w = pack_h2(x3.x * h1.z, x3.y * h1.w);
            } else {
                ua = make_uint4(0, 0, 0, 0);
                um = ua;
            }
            uint32_t off = swz(r, k0 * 2);
            *reinterpret_cast<uint4*>(smem + SM_A  + off) = ua;
            *reinterpret_cast<uint4*>(smem + SM_MU + off) = um;
        }
        __syncthreads();

        float c1[2][8][4], c2[2][8][4];
        #pragma unroll
        for (int i = 0; i < 2; ++i)
            #pragma unroll
            for (int j = 0; j < 8; ++j)
                #pragma unroll
                for (int q = 0; q < 4; ++q) { c1[i][j][q] = 0.f; c2[i][j][q] = 0.f; }

        for (int ks = 0; ks < 8; ++ks) {
            const int kb0 = ks * 32;
            uint32_t aA[2][4], aM[2][4];
            #pragma unroll
            for (int i = 0; i < 2; ++i) {
                uint32_t off = swz(mbase + i * 16 + (lane & 15), kb0 + ((lane >> 4) << 4));
                ldsm_x4(aA[i], sb + SM_A  + off);
                ldsm_x4(aM[i], sb + SM_MU + off);
            }
            #pragma unroll
            for (int j = 0; j < 8; ++j) {
                uint32_t boff = swz(nbase + j * 8 + (lane & 7), kb0 + (((lane >> 3) & 1) << 4));
                uint32_t bW1[2], bW2[2];
                ldsm_x2(bW1, sb + SM_W1 + boff);
                ldsm_x2(bW2, sb + SM_W2 + boff);
                #pragma unroll
                for (int i = 0; i < 2; ++i) {
                    mma16816(c1[i][j], aA[i], bW1);
                    mma16816(c2[i][j], aM[i], bW2);
                }
            }
        }

        const int rbase = row0 + mbase + (lane >> 2);
        #pragma unroll
        for (int j = 0; j < 8; ++j) {
            int col = nbase + j * 8 + 2 * (lane & 3);
            float2 bb1 = *reinterpret_cast<const float2*>(smem + SM_B1 + col * 4);
            float2 bb2 = *reinterpret_cast<const float2*>(smem + SM_B2 + col * 4);
            #pragma unroll
            for (int i = 0; i < 2; ++i) {
                int r0 = rbase + i * 16;
                if (r0 < n) {
                    float2 o;
                    o.x = lrelu(c1[i][j][0] + bb1.x) + lrelu(c2[i][j][0] + bb2.x);
                    o.y = lrelu(c1[i][j][1] + bb1.y) + lrelu(c2[i][j][1] + bb2.y);
                    *reinterpret_cast<float2*>(out + (size_t)r0 * D + col) = o;
                }
                int r1 = r0 + 8;
                if (r1 < n) {
                    float2 o;
                    o.x = lrelu(c1[i][j][2] + bb1.x) + lrelu(c2[i][j][2] + bb2.x);
                    o.y = lrelu(c1[i][j][3] + bb1.y) + lrelu(c2[i][j][3] + bb2.y);
                    *reinterpret_cast<float2*>(out + (size_t)r1 * D + col) = o;
                }
            }
        }
        __syncthreads();
    }
}

// ---------------------------------------------------------------------------
// Launch
// Inputs: x[N*128] f32, src[E] i32, dst[E] i32, e_attn[E] f32,
//         W1[128*128] f32, b1[128] f32, W2[128*128] f32, b2[128] f32
// ---------------------------------------------------------------------------
extern "C" void kernel_launch(void* const* d_in, const int* in_sizes, int n_in,
                              void* d_out, int out_size) {
    const float* x   = (const float*)d_in[0];
    const int*   src = (const int*)  d_in[1];
    const int*   dst = (const int*)  d_in[2];
    const float* ea  = (const float*)d_in[3];
    const float* W1  = (const float*)d_in[4];
    const float* b1  = (const float*)d_in[5];
    const float* W2  = (const float*)d_in[6];
    const float* b2  = (const float*)d_in[7];
    float*       out = (float*)d_out;

    const int n = in_sizes[0] / D;
    const int E = in_sizes[1];

    zero_cnt_kernel<<<256, 256>>>(n);
    convert_x_kernel<<<1024, 256>>>(x, n * D / 8);
    hist_kernel<<<(E + 255) / 256, 256>>>(dst, E);
    bsum_kernel<<<256, 256>>>(n);
    bscan_kernel<<<1, 256>>>(n);
    offwrite_kernel<<<256, 256>>>(n);
    fill_kernel<<<(E + 255) / 256, 256>>>(src, dst, ea, E);
    gather_kernel<<<(n + 7) / 8, 256>>>(n);

    cudaFuncSetAttribute(gemm_kernel,
                         cudaFuncAttributeMaxDynamicSharedMemorySize, SM_TOT);
    const int ntiles = (n + TILE_M - 1) / TILE_M;
    gemm_kernel<<<148, GT, SM_TOT>>>(W1, b1, W2, b2, out, n, ntiles);
}

// round 8
// speedup vs baseline: 2.5821x; 1.1690x over previous
#include <cuda_runtime.h>
#include <cuda_fp16.h>
#include <cstdint>

#define D        128
#define NMAX     100000
#define EMAX     1600000
#define TILE_M   128
#define GT       256     // gemm threads (8 warps)

// ---------------------------------------------------------------------------
// Device scratch
// ---------------------------------------------------------------------------
__device__ __half g_h[(size_t)NMAX * D];    // aggregated neighbor features (fp16)
__device__ __half g_xh[(size_t)NMAX * D];   // fp16 copy of x
__device__ int    g_cnt[NMAX];
__device__ int    g_off[NMAX + 1];
__device__ int    g_bsum[256];
__device__ int    g_rank[EMAX];             // within-dst rank of each edge
__device__ int2   g_epk[EMAX];              // packed {src, bits(e_attn)} sorted by dst

// ---------------------------------------------------------------------------
// x -> fp16 copy
// ---------------------------------------------------------------------------
__global__ void convert_x_kernel(const float* __restrict__ x, int n8) {
    for (int i = blockIdx.x * blockDim.x + threadIdx.x; i < n8;
         i += gridDim.x * blockDim.x) {
        const float* xp = x + (size_t)i * 8;
        float4 a = *reinterpret_cast<const float4*>(xp);
        float4 b = *reinterpret_cast<const float4*>(xp + 4);
        uint4 u;
        __half2 h;
        h = __float22half2_rn(make_float2(a.x, a.y)); u.x = *reinterpret_cast<uint32_t*>(&h);
        h = __float22half2_rn(make_float2(a.z, a.w)); u.y = *reinterpret_cast<uint32_t*>(&h);
        h = __float22half2_rn(make_float2(b.x, b.y)); u.z = *reinterpret_cast<uint32_t*>(&h);
        h = __float22half2_rn(make_float2(b.z, b.w)); u.w = *reinterpret_cast<uint32_t*>(&h);
        *reinterpret_cast<uint4*>(g_xh + (size_t)i * 8) = u;
    }
}

// ---------------------------------------------------------------------------
// CSR build
// ---------------------------------------------------------------------------
__global__ void zero_cnt_kernel(int n) {
    for (int i = blockIdx.x * blockDim.x + threadIdx.x; i < n;
         i += gridDim.x * blockDim.x)
        g_cnt[i] = 0;
}

// histogram + per-edge rank (sequential 4B write)
__global__ void hist_kernel(const int* __restrict__ dst, int E) {
    int e = blockIdx.x * blockDim.x + threadIdx.x;
    if (e < E) g_rank[e] = atomicAdd(&g_cnt[dst[e]], 1);
}

__global__ void bsum_kernel(int n) {
    __shared__ int sh[256];
    int chunk = (n + 255) >> 8;
    int lo = blockIdx.x * chunk;
    int hi = lo + chunk; if (hi > n) hi = n;
    int s = 0;
    for (int i = lo + threadIdx.x; i < hi; i += 256) s += g_cnt[i];
    sh[threadIdx.x] = s;
    __syncthreads();
    for (int d = 128; d; d >>= 1) {
        if (threadIdx.x < d) sh[threadIdx.x] += sh[threadIdx.x + d];
        __syncthreads();
    }
    if (threadIdx.x == 0) g_bsum[blockIdx.x] = sh[0];
}

// offsets: embedded scan of the 256 block sums (each block redundantly),
// then per-thread sub-chunk scan + sequential offset write.
__global__ void offwrite_kernel(int n) {
    __shared__ int sbm[256];
    __shared__ int sh[256];
    int bv = g_bsum[threadIdx.x];
    sbm[threadIdx.x] = bv;
    __syncthreads();
    for (int d = 1; d < 256; d <<= 1) {
        int t = (threadIdx.x >= d) ? sbm[threadIdx.x - d] : 0;
        __syncthreads();
        sbm[threadIdx.x] += t;
        __syncthreads();
    }
    if (blockIdx.x == 0 && threadIdx.x == 0) g_off[n] = sbm[255];
    int block_base = sbm[blockIdx.x] - g_bsum[blockIdx.x];   // exclusive

    int chunk = (n + 255) >> 8;
    int lo = blockIdx.x * chunk;
    int hi = lo + chunk; if (hi > n) hi = n;
    int sub = (chunk + 255) >> 8;
    int tlo = lo + threadIdx.x * sub;
    int thi = tlo + sub; if (thi > hi) thi = hi;
    int s = 0;
    for (int i = tlo; i < thi; ++i) s += g_cnt[i];
    sh[threadIdx.x] = s;
    __syncthreads();
    for (int d = 1; d < 256; d <<= 1) {
        int t = (threadIdx.x >= d) ? sh[threadIdx.x - d] : 0;
        __syncthreads();
        sh[threadIdx.x] += t;
        __syncthreads();
    }
    int run = block_base + sh[threadIdx.x] - s;
    for (int i = tlo; i < thi; ++i) {
        g_off[i] = run;
        run += g_cnt[i];
    }
}

// atomic-free fill: p = off[dst] + rank
__global__ void fill_kernel(const int* __restrict__ src, const int* __restrict__ dst,
                            const float* __restrict__ ea, int E) {
    int e = blockIdx.x * blockDim.x + threadIdx.x;
    if (e < E) {
        int p = g_off[dst[e]] + g_rank[e];
        g_epk[p] = make_int2(src[e], __float_as_int(ea[e]));
    }
}

// ---------------------------------------------------------------------------
// Gather: one warp per node, fp16 rows (256B/edge), fp32 accumulation,
// unroll-4 for MLP; fp16 result store.
// ---------------------------------------------------------------------------
__device__ __forceinline__ void acc_edge(float4& acc, uint2 v, float w) {
    float2 a0 = __half22float2(*reinterpret_cast<__half2*>(&v.x));
    float2 a1 = __half22float2(*reinterpret_cast<__half2*>(&v.y));
    acc.x = fmaf(w, a0.x, acc.x); acc.y = fmaf(w, a0.y, acc.y);
    acc.z = fmaf(w, a1.x, acc.z); acc.w = fmaf(w, a1.y, acc.w);
}

__global__ void gather_kernel(int n) {
    int w = (blockIdx.x * blockDim.x + threadIdx.x) >> 5;
    if (w >= n) return;
    int lane = threadIdx.x & 31;
    int j   = g_off[w];
    int end = g_off[w + 1];
    const uint2* xb = reinterpret_cast<const uint2*>(g_xh);
    float4 acc = make_float4(0.f, 0.f, 0.f, 0.f);

    #pragma unroll 1
    for (; j + 4 <= end; j += 4) {
        int2 p0 = g_epk[j];
        int2 p1 = g_epk[j + 1];
        int2 p2 = g_epk[j + 2];
        int2 p3 = g_epk[j + 3];
        uint2 v0 = __ldg(xb + (size_t)p0.x * 32 + lane);
        uint2 v1 = __ldg(xb + (size_t)p1.x * 32 + lane);
        uint2 v2 = __ldg(xb + (size_t)p2.x * 32 + lane);
        uint2 v3 = __ldg(xb + (size_t)p3.x * 32 + lane);
        acc_edge(acc, v0, __int_as_float(p0.y));
        acc_edge(acc, v1, __int_as_float(p1.y));
        acc_edge(acc, v2, __int_as_float(p2.y));
        acc_edge(acc, v3, __int_as_float(p3.y));
    }
    #pragma unroll 1
    for (; j < end; ++j) {
        int2 p0 = g_epk[j];
        uint2 v0 = __ldg(xb + (size_t)p0.x * 32 + lane);
        acc_edge(acc, v0, __int_as_float(p0.y));
    }

    uint2 o;
    __half2 h;
    h = __float22half2_rn(make_float2(acc.x, acc.y)); o.x = *reinterpret_cast<uint32_t*>(&h);
    h = __float22half2_rn(make_float2(acc.z, acc.w)); o.y = *reinterpret_cast<uint32_t*>(&h);
    reinterpret_cast<uint2*>(g_h)[(size_t)w * 32 + lane] = o;
}

// ---------------------------------------------------------------------------
// HMMA GEMM: out = lrelu((x+h)@W1^T + b1) + lrelu((x*h)@W2^T + b2)
// fp16 operands, fp32 accumulation via mma.sync.m16n8k16.
// ---------------------------------------------------------------------------
#define SM_W1   0
#define SM_W2   32768
#define SM_A    65536
#define SM_MU   98304
#define SM_B1   131072
#define SM_B2   131584
#define SM_TOT  132096

__device__ __forceinline__ uint32_t swz(int row, int kb) {
    return (uint32_t)(row * 256 + (kb ^ ((row & 7) << 4)));
}

__device__ __forceinline__ uint32_t pack_h2(float a, float b) {
    __half2 h = __float22half2_rn(make_float2(a, b));
    return *reinterpret_cast<uint32_t*>(&h);
}

__device__ __forceinline__ float lrelu(float v) {
    return v >= 0.f ? v : 0.01f * v;
}

__device__ __forceinline__ void ldsm_x4(uint32_t* r, uint32_t addr) {
    asm volatile("ldmatrix.sync.aligned.m8n8.x4.shared.b16 {%0,%1,%2,%3}, [%4];"
                 : "=r"(r[0]), "=r"(r[1]), "=r"(r[2]), "=r"(r[3]) : "r"(addr));
}
__device__ __forceinline__ void ldsm_x2(uint32_t* r, uint32_t addr) {
    asm volatile("ldmatrix.sync.aligned.m8n8.x2.shared.b16 {%0,%1}, [%2];"
                 : "=r"(r[0]), "=r"(r[1]) : "r"(addr));
}
__device__ __forceinline__ void mma16816(float* c, const uint32_t* a, const uint32_t* b) {
    asm volatile(
        "mma.sync.aligned.m16n8k16.row.col.f32.f16.f16.f32 "
        "{%0,%1,%2,%3}, {%4,%5,%6,%7}, {%8,%9}, {%0,%1,%2,%3};"
        : "+f"(c[0]), "+f"(c[1]), "+f"(c[2]), "+f"(c[3])
        : "r"(a[0]), "r"(a[1]), "r"(a[2]), "r"(a[3]), "r"(b[0]), "r"(b[1]));
}

__device__ __forceinline__ uint32_t hadd2u(uint32_t a, uint32_t b) {
    __half2 r = __hadd2(*reinterpret_cast<__half2*>(&a), *reinterpret_cast<__half2*>(&b));
    return *reinterpret_cast<uint32_t*>(&r);
}
__device__ __forceinline__ uint32_t hmul2u(uint32_t a, uint32_t b) {
    __half2 r = __hmul2(*reinterpret_cast<__half2*>(&a), *reinterpret_cast<__half2*>(&b));
    return *reinterpret_cast<uint32_t*>(&r);
}

__global__ __launch_bounds__(GT, 1)
void gemm_kernel(const float* __restrict__ W1, const float* __restrict__ b1,
                 const float* __restrict__ W2, const float* __restrict__ b2,
                 float* __restrict__ out, int n, int ntiles) {
    extern __shared__ char smem[];
    uint32_t sb = (uint32_t)__cvta_generic_to_shared(smem);
    const int tid  = threadIdx.x;
    const int wid  = tid >> 5;
    const int lane = tid & 31;
    const int mbase = (wid >> 1) * 32;
    const int nbase = (wid & 1) * 64;

    // Stage W1, W2 as fp16 (swizzled), biases as f32
    for (int i = tid; i < D * D / 8; i += GT) {
        int row = i >> 4;
        int k0  = (i & 15) << 3;
        const float* w1p = W1 + row * D + k0;
        const float* w2p = W2 + row * D + k0;
        float4 a0 = *reinterpret_cast<const float4*>(w1p);
        float4 a1 = *reinterpret_cast<const float4*>(w1p + 4);
        float4 c0 = *reinterpret_cast<const float4*>(w2p);
        float4 c1 = *reinterpret_cast<const float4*>(w2p + 4);
        uint4 u1, u2;
        u1.x = pack_h2(a0.x, a0.y); u1.y = pack_h2(a0.z, a0.w);
        u1.z = pack_h2(a1.x, a1.y); u1.w = pack_h2(a1.z, a1.w);
        u2.x = pack_h2(c0.x, c0.y); u2.y = pack_h2(c0.z, c0.w);
        u2.z = pack_h2(c1.x, c1.y); u2.w = pack_h2(c1.z, c1.w);
        uint32_t off = swz(row, k0 * 2);
        *reinterpret_cast<uint4*>(smem + SM_W1 + off) = u1;
        *reinterpret_cast<uint4*>(smem + SM_W2 + off) = u2;
    }
    if (tid < D) {
        *reinterpret_cast<float*>(smem + SM_B1 + tid * 4) = b1[tid];
        *reinterpret_cast<float*>(smem + SM_B2 + tid * 4) = b2[tid];
    }
    __syncthreads();

    for (int tile = blockIdx.x; tile < ntiles; tile += gridDim.x) {
        const int row0 = tile * TILE_M;

        // Stage A = x+h, MU = x*h (all fp16, half2 arithmetic)
        for (int i = tid; i < TILE_M * 16; i += GT) {
            int r  = i >> 4;
            int k0 = (i & 15) << 3;
            int grow = row0 + r;
            uint4 ua, um;
            if (grow < n) {
                uint4 xv = *reinterpret_cast<const uint4*>(g_xh + (size_t)grow * D + k0);
                uint4 hv = *reinterpret_cast<const uint4*>(g_h  + (size_t)grow * D + k0);
                ua.x = hadd2u(xv.x, hv.x); ua.y = hadd2u(xv.y, hv.y);
                ua.z = hadd2u(xv.z, hv.z); ua.w = hadd2u(xv.w, hv.w);
                um.x = hmul2u(xv.x, hv.x); um.y = hmul2u(xv.y, hv.y);
                um.z = hmul2u(xv.z, hv.z); um.w = hmul2u(xv.w, hv.w);
            } else {
                ua = make_uint4(0, 0, 0, 0);
                um = ua;
            }
            uint32_t off = swz(r, k0 * 2);
            *reinterpret_cast<uint4*>(smem + SM_A  + off) = ua;
            *reinterpret_cast<uint4*>(smem + SM_MU + off) = um;
        }
        __syncthreads();

        float c1[2][8][4], c2[2][8][4];
        #pragma unroll
        for (int i = 0; i < 2; ++i)
            #pragma unroll
            for (int j = 0; j < 8; ++j)
                #pragma unroll
                for (int q = 0; q < 4; ++q) { c1[i][j][q] = 0.f; c2[i][j][q] = 0.f; }

        for (int ks = 0; ks < 8; ++ks) {
            const int kb0 = ks * 32;
            uint32_t aA[2][4], aM[2][4];
            #pragma unroll
            for (int i = 0; i < 2; ++i) {
                uint32_t off = swz(mbase + i * 16 + (lane & 15), kb0 + ((lane >> 4) << 4));
                ldsm_x4(aA[i], sb + SM_A  + off);
                ldsm_x4(aM[i], sb + SM_MU + off);
            }
            #pragma unroll
            for (int j = 0; j < 8; ++j) {
                uint32_t boff = swz(nbase + j * 8 + (lane & 7), kb0 + (((lane >> 3) & 1) << 4));
                uint32_t bW1[2], bW2[2];
                ldsm_x2(bW1, sb + SM_W1 + boff);
                ldsm_x2(bW2, sb + SM_W2 + boff);
                #pragma unroll
                for (int i = 0; i < 2; ++i) {
                    mma16816(c1[i][j], aA[i], bW1);
                    mma16816(c2[i][j], aM[i], bW2);
                }
            }
        }

        const int rbase = row0 + mbase + (lane >> 2);
        #pragma unroll
        for (int j = 0; j < 8; ++j) {
            int col = nbase + j * 8 + 2 * (lane & 3);
            float2 bb1 = *reinterpret_cast<const float2*>(smem + SM_B1 + col * 4);
            float2 bb2 = *reinterpret_cast<const float2*>(smem + SM_B2 + col * 4);
            #pragma unroll
            for (int i = 0; i < 2; ++i) {
                int r0 = rbase + i * 16;
                if (r0 < n) {
                    float2 o;
                    o.x = lrelu(c1[i][j][0] + bb1.x) + lrelu(c2[i][j][0] + bb2.x);
                    o.y = lrelu(c1[i][j][1] + bb1.y) + lrelu(c2[i][j][1] + bb2.y);
                    *reinterpret_cast<float2*>(out + (size_t)r0 * D + col) = o;
                }
                int r1 = r0 + 8;
                if (r1 < n) {
                    float2 o;
                    o.x = lrelu(c1[i][j][2] + bb1.x) + lrelu(c2[i][j][2] + bb2.x);
                    o.y = lrelu(c1[i][j][3] + bb1.y) + lrelu(c2[i][j][3] + bb2.y);
                    *reinterpret_cast<float2*>(out + (size_t)r1 * D + col) = o;
                }
            }
        }
        __syncthreads();
    }
}

// ---------------------------------------------------------------------------
// Launch
// Inputs: x[N*128] f32, src[E] i32, dst[E] i32, e_attn[E] f32,
//         W1[128*128] f32, b1[128] f32, W2[128*128] f32, b2[128] f32
// ---------------------------------------------------------------------------
extern "C" void kernel_launch(void* const* d_in, const int* in_sizes, int n_in,
                              void* d_out, int out_size) {
    const float* x   = (const float*)d_in[0];
    const int*   src = (const int*)  d_in[1];
    const int*   dst = (const int*)  d_in[2];
    const float* ea  = (const float*)d_in[3];
    const float* W1  = (const float*)d_in[4];
    const float* b1  = (const float*)d_in[5];
    const float* W2  = (const float*)d_in[6];
    const float* b2  = (const float*)d_in[7];
    float*       out = (float*)d_out;

    const int n = in_sizes[0] / D;
    const int E = in_sizes[1];

    zero_cnt_kernel<<<256, 256>>>(n);
    convert_x_kernel<<<1024, 256>>>(x, n * D / 8);
    hist_kernel<<<(E + 255) / 256, 256>>>(dst, E);
    bsum_kernel<<<256, 256>>>(n);
    offwrite_kernel<<<256, 256>>>(n);
    fill_kernel<<<(E + 255) / 256, 256>>>(src, dst, ea, E);
    gather_kernel<<<(n + 7) / 8, 256>>>(n);

    cudaFuncSetAttribute(gemm_kernel,
                         cudaFuncAttributeMaxDynamicSharedMemorySize, SM_TOT);
    const int ntiles = (n + TILE_M - 1) / TILE_M;
    gemm_kernel<<<148, GT, SM_TOT>>>(W1, b1, W2, b2, out, n, ntiles);
}

// round 10
// speedup vs baseline: 3.0623x; 1.1860x over previous
#include <cuda_runtime.h>
#include <cuda_fp16.h>
#include <cstdint>

#define D        128
#define NMAX     100000
#define EMAX     1600000
#define TILE_M   128
#define GT       256     // gemm threads (8 warps)

// ---------------------------------------------------------------------------
// Device scratch
// ---------------------------------------------------------------------------
__device__ __half g_h[(size_t)NMAX * D];    // aggregated neighbor features (fp16)
__device__ __half g_xh[(size_t)NMAX * D];   // fp16 copy of x
__device__ int    g_cnt[NMAX];
__device__ int    g_off[NMAX + 1];
__device__ int    g_bsum[256];
__device__ int    g_rank[EMAX];             // within-dst rank of each edge
__device__ int2   g_epk[EMAX];              // packed {src, bits(e_attn)} sorted by dst

// ---------------------------------------------------------------------------
// prep: x -> fp16 copy, zero counts (merged)
// ---------------------------------------------------------------------------
__global__ void prep_kernel(const float* __restrict__ x, int n8, int n) {
    int stride = gridDim.x * blockDim.x;
    for (int i = blockIdx.x * blockDim.x + threadIdx.x; i < n8; i += stride) {
        const float* xp = x + (size_t)i * 8;
        float4 a = *reinterpret_cast<const float4*>(xp);
        float4 b = *reinterpret_cast<const float4*>(xp + 4);
        uint4 u;
        __half2 h;
        h = __float22half2_rn(make_float2(a.x, a.y)); u.x = *reinterpret_cast<uint32_t*>(&h);
        h = __float22half2_rn(make_float2(a.z, a.w)); u.y = *reinterpret_cast<uint32_t*>(&h);
        h = __float22half2_rn(make_float2(b.x, b.y)); u.z = *reinterpret_cast<uint32_t*>(&h);
        h = __float22half2_rn(make_float2(b.z, b.w)); u.w = *reinterpret_cast<uint32_t*>(&h);
        *reinterpret_cast<uint4*>(g_xh + (size_t)i * 8) = u;
    }
    for (int i = blockIdx.x * blockDim.x + threadIdx.x; i < n; i += stride)
        g_cnt[i] = 0;
}

// ---------------------------------------------------------------------------
// CSR build
// ---------------------------------------------------------------------------
__global__ void hist_kernel(const int* __restrict__ dst, int E) {
    int e = blockIdx.x * blockDim.x + threadIdx.x;
    if (e < E) g_rank[e] = atomicAdd(&g_cnt[dst[e]], 1);
}

__global__ void bsum_kernel(int n) {
    __shared__ int sh[256];
    int chunk = (n + 255) >> 8;
    int lo = blockIdx.x * chunk;
    int hi = lo + chunk; if (hi > n) hi = n;
    int s = 0;
    for (int i = lo + threadIdx.x; i < hi; i += 256) s += g_cnt[i];
    sh[threadIdx.x] = s;
    __syncthreads();
    for (int d = 128; d; d >>= 1) {
        if (threadIdx.x < d) sh[threadIdx.x] += sh[threadIdx.x + d];
        __syncthreads();
    }
    if (threadIdx.x == 0) g_bsum[blockIdx.x] = sh[0];
}

__global__ void offwrite_kernel(int n) {
    __shared__ int sbm[256];
    __shared__ int sh[256];
    int bv = g_bsum[threadIdx.x];
    sbm[threadIdx.x] = bv;
    __syncthreads();
    for (int d = 1; d < 256; d <<= 1) {
        int t = (threadIdx.x >= d) ? sbm[threadIdx.x - d] : 0;
        __syncthreads();
        sbm[threadIdx.x] += t;
        __syncthreads();
    }
    if (blockIdx.x == 0 && threadIdx.x == 0) g_off[n] = sbm[255];
    int block_base = sbm[blockIdx.x] - g_bsum[blockIdx.x];   // exclusive

    int chunk = (n + 255) >> 8;
    int lo = blockIdx.x * chunk;
    int hi = lo + chunk; if (hi > n) hi = n;
    int sub = (chunk + 255) >> 8;
    int tlo = lo + threadIdx.x * sub;
    int thi = tlo + sub; if (thi > hi) thi = hi;
    int s = 0;
    for (int i = tlo; i < thi; ++i) s += g_cnt[i];
    sh[threadIdx.x] = s;
    __syncthreads();
    for (int d = 1; d < 256; d <<= 1) {
        int t = (threadIdx.x >= d) ? sh[threadIdx.x - d] : 0;
        __syncthreads();
        sh[threadIdx.x] += t;
        __syncthreads();
    }
    int run = block_base + sh[threadIdx.x] - s;
    for (int i = tlo; i < thi; ++i) {
        g_off[i] = run;
        run += g_cnt[i];
    }
}

__global__ void fill_kernel(const int* __restrict__ src, const int* __restrict__ dst,
                            const float* __restrict__ ea, int E) {
    int e = blockIdx.x * blockDim.x + threadIdx.x;
    if (e < E) {
        int p = g_off[dst[e]] + g_rank[e];
        g_epk[p] = make_int2(src[e], __float_as_int(ea[e]));
    }
}

// ---------------------------------------------------------------------------
// Gather: half-warp (16 lanes) per node; uint4 (16B) per lane covers 256B row.
// fp32 accumulation, unroll-4 for MLP, fp16 result store.
// ---------------------------------------------------------------------------
__device__ __forceinline__ void acc_edge4(float* acc, uint4 v, float w) {
    float2 a0 = __half22float2(*reinterpret_cast<__half2*>(&v.x));
    float2 a1 = __half22float2(*reinterpret_cast<__half2*>(&v.y));
    float2 a2 = __half22float2(*reinterpret_cast<__half2*>(&v.z));
    float2 a3 = __half22float2(*reinterpret_cast<__half2*>(&v.w));
    acc[0] = fmaf(w, a0.x, acc[0]); acc[1] = fmaf(w, a0.y, acc[1]);
    acc[2] = fmaf(w, a1.x, acc[2]); acc[3] = fmaf(w, a1.y, acc[3]);
    acc[4] = fmaf(w, a2.x, acc[4]); acc[5] = fmaf(w, a2.y, acc[5]);
    acc[6] = fmaf(w, a3.x, acc[6]); acc[7] = fmaf(w, a3.y, acc[7]);
}

__global__ void gather_kernel(int n) {
    int idx  = blockIdx.x * blockDim.x + threadIdx.x;
    int w    = idx >> 4;
    if (w >= n) return;
    int lane = idx & 15;
    int j   = g_off[w];
    int end = g_off[w + 1];
    const uint4* xb = reinterpret_cast<const uint4*>(g_xh);   // 16 uint4 per row
    float acc[8] = {0.f, 0.f, 0.f, 0.f, 0.f, 0.f, 0.f, 0.f};

    #pragma unroll 1
    for (; j + 4 <= end; j += 4) {
        int2 p0 = g_epk[j];
        int2 p1 = g_epk[j + 1];
        int2 p2 = g_epk[j + 2];
        int2 p3 = g_epk[j + 3];
        uint4 v0 = __ldg(xb + (size_t)p0.x * 16 + lane);
        uint4 v1 = __ldg(xb + (size_t)p1.x * 16 + lane);
        uint4 v2 = __ldg(xb + (size_t)p2.x * 16 + lane);
        uint4 v3 = __ldg(xb + (size_t)p3.x * 16 + lane);
        acc_edge4(acc, v0, __int_as_float(p0.y));
        acc_edge4(acc, v1, __int_as_float(p1.y));
        acc_edge4(acc, v2, __int_as_float(p2.y));
        acc_edge4(acc, v3, __int_as_float(p3.y));
    }
    #pragma unroll 1
    for (; j < end; ++j) {
        int2 p0 = g_epk[j];
        uint4 v0 = __ldg(xb + (size_t)p0.x * 16 + lane);
        acc_edge4(acc, v0, __int_as_float(p0.y));
    }

    uint4 o;
    __half2 h;
    h = __float22half2_rn(make_float2(acc[0], acc[1])); o.x = *reinterpret_cast<uint32_t*>(&h);
    h = __float22half2_rn(make_float2(acc[2], acc[3])); o.y = *reinterpret_cast<uint32_t*>(&h);
    h = __float22half2_rn(make_float2(acc[4], acc[5])); o.z = *reinterpret_cast<uint32_t*>(&h);
    h = __float22half2_rn(make_float2(acc[6], acc[7])); o.w = *reinterpret_cast<uint32_t*>(&h);
    reinterpret_cast<uint4*>(g_h)[(size_t)w * 16 + lane] = o;
}

// ---------------------------------------------------------------------------
// HMMA GEMM: out = lrelu((x+h)@W1^T + b1) + lrelu((x*h)@W2^T + b2)
// cp.async double-buffered RAW xh/h tiles; bi-interaction computed on
// ldmatrix fragments (hadd2/hmul2) — bitwise identical to pre-staged A/M.
// ---------------------------------------------------------------------------
#define SM_W1   0
#define SM_W2   32768
#define SM_TILE 65536          // 2 buffers x (xh 32KB + h 32KB)
#define SM_B1   (SM_TILE + 131072)
#define SM_B2   (SM_B1 + 512)
#define SM_TOT  (SM_B2 + 512)  // 197632 bytes

__device__ __forceinline__ uint32_t swz(int row, int kb) {
    return (uint32_t)(row * 256 + (kb ^ ((row & 7) << 4)));
}

__device__ __forceinline__ uint32_t pack_h2(float a, float b) {
    __half2 h = __float22half2_rn(make_float2(a, b));
    return *reinterpret_cast<uint32_t*>(&h);
}

__device__ __forceinline__ float lrelu(float v) {
    return v >= 0.f ? v : 0.01f * v;
}

__device__ __forceinline__ void ldsm_x4(uint32_t* r, uint32_t addr) {
    asm volatile("ldmatrix.sync.aligned.m8n8.x4.shared.b16 {%0,%1,%2,%3}, [%4];"
                 : "=r"(r[0]), "=r"(r[1]), "=r"(r[2]), "=r"(r[3]) : "r"(addr));
}
__device__ __forceinline__ void ldsm_x2(uint32_t* r, uint32_t addr) {
    asm volatile("ldmatrix.sync.aligned.m8n8.x2.shared.b16 {%0,%1}, [%2];"
                 : "=r"(r[0]), "=r"(r[1]) : "r"(addr));
}
__device__ __forceinline__ void mma16816(float* c, const uint32_t* a, const uint32_t* b) {
    asm volatile(
        "mma.sync.aligned.m16n8k16.row.col.f32.f16.f16.f32 "
        "{%0,%1,%2,%3}, {%4,%5,%6,%7}, {%8,%9}, {%0,%1,%2,%3};"
        : "+f"(c[0]), "+f"(c[1]), "+f"(c[2]), "+f"(c[3])
        : "r"(a[0]), "r"(a[1]), "r"(a[2]), "r"(a[3]), "r"(b[0]), "r"(b[1]));
}

__device__ __forceinline__ uint32_t hadd2u(uint32_t a, uint32_t b) {
    __half2 r = __hadd2(*reinterpret_cast<__half2*>(&a), *reinterpret_cast<__half2*>(&b));
    return *reinterpret_cast<uint32_t*>(&r);
}
__device__ __forceinline__ uint32_t hmul2u(uint32_t a, uint32_t b) {
    __half2 r = __hmul2(*reinterpret_cast<__half2*>(&a), *reinterpret_cast<__half2*>(&b));
    return *reinterpret_cast<uint32_t*>(&r);
}

#define CP16(dst, src) \
    asm volatile("cp.async.cg.shared.global [%0], [%1], 16;" :: "r"(dst), "l"(src))
#define CP_COMMIT() asm volatile("cp.async.commit_group;" ::: "memory")
#define CP_WAIT(N)  asm volatile("cp.async.wait_group %0;" :: "n"(N) : "memory")

// Stage one raw tile pair (xh + h) via cp.async into buffer buf.
__device__ __forceinline__ void stage_tile(uint32_t sb, int buf, int row0,
                                           int n, int tid) {
    uint32_t base_xh = SM_TILE + (uint32_t)buf * 65536;
    uint32_t base_h  = base_xh + 32768;
    #pragma unroll
    for (int it = 0; it < 8; ++it) {
        int i = tid + it * GT;            // 0..2047 chunk index
        int r = i >> 4;
        int c = i & 15;                   // 16B chunk within row
        int grow = row0 + r;
        if (grow >= n) grow = n - 1;      // clamp; garbage rows masked at store
        uint32_t off = swz(r, c << 4);
        const __half* xs = g_xh + (size_t)grow * D + c * 8;
        const __half* hs = g_h  + (size_t)grow * D + c * 8;
        CP16(sb + base_xh + off, xs);
        CP16(sb + base_h  + off, hs);
    }
}

__global__ __launch_bounds__(GT, 1)
void gemm_kernel(const float* __restrict__ W1, const float* __restrict__ b1,
                 const float* __restrict__ W2, const float* __restrict__ b2,
                 float* __restrict__ out, int n, int ntiles) {
    extern __shared__ char smem[];
    uint32_t sb = (uint32_t)__cvta_generic_to_shared(smem);
    const int tid  = threadIdx.x;
    const int wid  = tid >> 5;
    const int lane = tid & 31;
    const int mbase = (wid >> 1) * 32;
    const int nbase = (wid & 1) * 64;

    // Stage W1, W2 as fp16 (swizzled), biases as f32
    for (int i = tid; i < D * D / 8; i += GT) {
        int row = i >> 4;
        int k0  = (i & 15) << 3;
        const float* w1p = W1 + row * D + k0;
        const float* w2p = W2 + row * D + k0;
        float4 a0 = *reinterpret_cast<const float4*>(w1p);
        float4 a1 = *reinterpret_cast<const float4*>(w1p + 4);
        float4 c0 = *reinterpret_cast<const float4*>(w2p);
        float4 c1 = *reinterpret_cast<const float4*>(w2p + 4);
        uint4 u1, u2;
        u1.x = pack_h2(a0.x, a0.y); u1.y = pack_h2(a0.z, a0.w);
        u1.z = pack_h2(a1.x, a1.y); u1.w = pack_h2(a1.z, a1.w);
        u2.x = pack_h2(c0.x, c0.y); u2.y = pack_h2(c0.z, c0.w);
        u2.z = pack_h2(c1.x, c1.y); u2.w = pack_h2(c1.z, c1.w);
        uint32_t off = swz(row, k0 * 2);
        *reinterpret_cast<uint4*>(smem + SM_W1 + off) = u1;
        *reinterpret_cast<uint4*>(smem + SM_W2 + off) = u2;
    }
    if (tid < D) {
        *reinterpret_cast<float*>(smem + SM_B1 + tid * 4) = b1[tid];
        *reinterpret_cast<float*>(smem + SM_B2 + tid * 4) = b2[tid];
    }

    // Prologue: stage first tile into buffer 0
    if (blockIdx.x < ntiles) {
        stage_tile(sb, 0, blockIdx.x * TILE_M, n, tid);
    }
    CP_COMMIT();

    int b = 0;
    for (int tile = blockIdx.x; tile < ntiles; tile += gridDim.x) {
        const int row0 = tile * TILE_M;
        const int nxt  = tile + gridDim.x;

        if (nxt < ntiles) {
            stage_tile(sb, b ^ 1, nxt * TILE_M, n, tid);
            CP_COMMIT();
            CP_WAIT(1);
        } else {
            CP_WAIT(0);
        }
        __syncthreads();

        const uint32_t base_xh = SM_TILE + (uint32_t)b * 65536;
        const uint32_t base_h  = base_xh + 32768;

        float c1[2][8][4], c2[2][8][4];
        #pragma unroll
        for (int i = 0; i < 2; ++i)
            #pragma unroll
            for (int j = 0; j < 8; ++j)
                #pragma unroll
                for (int q = 0; q < 4; ++q) { c1[i][j][q] = 0.f; c2[i][j][q] = 0.f; }

        for (int ks = 0; ks < 8; ++ks) {
            const int kb0 = ks * 32;
            uint32_t aA[2][4], aM[2][4];
            #pragma unroll
            for (int i = 0; i < 2; ++i) {
                uint32_t off = swz(mbase + i * 16 + (lane & 15), kb0 + ((lane >> 4) << 4));
                uint32_t xf[4], hf[4];
                ldsm_x4(xf, sb + base_xh + off);
                ldsm_x4(hf, sb + base_h  + off);
                #pragma unroll
                for (int q = 0; q < 4; ++q) {
                    aA[i][q] = hadd2u(xf[q], hf[q]);
                    aM[i][q] = hmul2u(xf[q], hf[q]);
                }
            }
            #pragma unroll
            for (int j = 0; j < 8; ++j) {
                uint32_t boff = swz(nbase + j * 8 + (lane & 7), kb0 + (((lane >> 3) & 1) << 4));
                uint32_t bW1[2], bW2[2];
                ldsm_x2(bW1, sb + SM_W1 + boff);
                ldsm_x2(bW2, sb + SM_W2 + boff);
                #pragma unroll
                for (int i = 0; i < 2; ++i) {
                    mma16816(c1[i][j], aA[i], bW1);
                    mma16816(c2[i][j], aM[i], bW2);
                }
            }
        }

        const int rbase = row0 + mbase + (lane >> 2);
        #pragma unroll
        for (int j = 0; j < 8; ++j) {
            int col = nbase + j * 8 + 2 * (lane & 3);
            float2 bb1 = *reinterpret_cast<const float2*>(smem + SM_B1 + col * 4);
            float2 bb2 = *reinterpret_cast<const float2*>(smem + SM_B2 + col * 4);
            #pragma unroll
            for (int i = 0; i < 2; ++i) {
                int r0 = rbase + i * 16;
                if (r0 < n) {
                    float2 o;
                    o.x = lrelu(c1[i][j][0] + bb1.x) + lrelu(c2[i][j][0] + bb2.x);
                    o.y = lrelu(c1[i][j][1] + bb1.y) + lrelu(c2[i][j][1] + bb2.y);
                    *reinterpret_cast<float2*>(out + (size_t)r0 * D + col) = o;
                }
                int r1 = r0 + 8;
                if (r1 < n) {
                    float2 o;
                    o.x = lrelu(c1[i][j][2] + bb1.x) + lrelu(c2[i][j][2] + bb2.x);
                    o.y = lrelu(c1[i][j][3] + bb1.y) + lrelu(c2[i][j][3] + bb2.y);
                    *reinterpret_cast<float2*>(out + (size_t)r1 * D + col) = o;
                }
            }
        }
        __syncthreads();
        b ^= 1;
    }
}

// ---------------------------------------------------------------------------
// Launch
// Inputs: x[N*128] f32, src[E] i32, dst[E] i32, e_attn[E] f32,
//         W1[128*128] f32, b1[128] f32, W2[128*128] f32, b2[128] f32
// ---------------------------------------------------------------------------
extern "C" void kernel_launch(void* const* d_in, const int* in_sizes, int n_in,
                              void* d_out, int out_size) {
    const float* x   = (const float*)d_in[0];
    const int*   src = (const int*)  d_in[1];
    const int*   dst = (const int*)  d_in[2];
    const float* ea  = (const float*)d_in[3];
    const float* W1  = (const float*)d_in[4];
    const float* b1  = (const float*)d_in[5];
    const float* W2  = (const float*)d_in[6];
    const float* b2  = (const float*)d_in[7];
    float*       out = (float*)d_out;

    const int n = in_sizes[0] / D;
    const int E = in_sizes[1];

    prep_kernel<<<1024, 256>>>(x, n * D / 8, n);
    hist_kernel<<<(E + 255) / 256, 256>>>(dst, E);
    bsum_kernel<<<256, 256>>>(n);
    offwrite_kernel<<<256, 256>>>(n);
    fill_kernel<<<(E + 255) / 256, 256>>>(src, dst, ea, E);
    gather_kernel<<<(n + 15) / 16, 256>>>(n);

    cudaFuncSetAttribute(gemm_kernel,
                         cudaFuncAttributeMaxDynamicSharedMemorySize, SM_TOT);
    const int ntiles = (n + TILE_M - 1) / TILE_M;
    gemm_kernel<<<148, GT, SM_TOT>>>(W1, b1, W2, b2, out, n, ntiles);
}

// round 11
// speedup vs baseline: 3.1224x; 1.0196x over previous
#include <cuda_runtime.h>
#include <cuda_fp16.h>
#include <cstdint>

#define D        128
#define NMAX     100000
#define EMAX     1600000
#define TILE_M   128
#define GT       256     // gemm threads (8 warps)

// ---------------------------------------------------------------------------
// Device scratch
// ---------------------------------------------------------------------------
__device__ __half g_h[(size_t)NMAX * D];    // aggregated neighbor features (fp16)
__device__ __half g_xh[(size_t)NMAX * D];   // fp16 copy of x
__device__ int    g_cnt[NMAX];
__device__ int    g_off[NMAX + 1];
__device__ int    g_bsum[256];
__device__ int    g_barrier;
__device__ int    g_rank[EMAX];             // within-dst rank of each edge
__device__ int2   g_epk[EMAX];              // packed {src, bits(e_attn)} sorted by dst

// ---------------------------------------------------------------------------
// zero counts + spin-barrier counter
// ---------------------------------------------------------------------------
__global__ void zero_cnt_kernel(int n) {
    int i0 = blockIdx.x * blockDim.x + threadIdx.x;
    if (i0 == 0) g_barrier = 0;
    for (int i = i0; i < n; i += gridDim.x * blockDim.x)
        g_cnt[i] = 0;
}

// ---------------------------------------------------------------------------
// x -> fp16 copy (runs on side stream, overlapped with CSR build)
// ---------------------------------------------------------------------------
__global__ void convert_x_kernel(const float* __restrict__ x, int n8) {
    for (int i = blockIdx.x * blockDim.x + threadIdx.x; i < n8;
         i += gridDim.x * blockDim.x) {
        const float* xp = x + (size_t)i * 8;
        float4 a = *reinterpret_cast<const float4*>(xp);
        float4 b = *reinterpret_cast<const float4*>(xp + 4);
        uint4 u;
        __half2 h;
        h = __float22half2_rn(make_float2(a.x, a.y)); u.x = *reinterpret_cast<uint32_t*>(&h);
        h = __float22half2_rn(make_float2(a.z, a.w)); u.y = *reinterpret_cast<uint32_t*>(&h);
        h = __float22half2_rn(make_float2(b.x, b.y)); u.z = *reinterpret_cast<uint32_t*>(&h);
        h = __float22half2_rn(make_float2(b.z, b.w)); u.w = *reinterpret_cast<uint32_t*>(&h);
        *reinterpret_cast<uint4*>(g_xh + (size_t)i * 8) = u;
    }
}

// ---------------------------------------------------------------------------
// CSR build
// ---------------------------------------------------------------------------
__global__ void hist_kernel(const int* __restrict__ dst, int E) {
    int e = blockIdx.x * blockDim.x + threadIdx.x;
    if (e < E) g_rank[e] = atomicAdd(&g_cnt[dst[e]], 1);
}

// merged bsum + offwrite with global spin barrier (256 blocks, all resident)
__global__ void scanoff_kernel(int n) {
    __shared__ int sbm[256];
    __shared__ int sh[256];
    const int tid = threadIdx.x;
    const int chunk = (n + 255) >> 8;
    const int lo = blockIdx.x * chunk;
    int hi = lo + chunk; if (hi > n) hi = n;

    // phase 1: per-thread sub-chunk sums (reused in phase 2) -> block sum
    const int sub = (chunk + 255) >> 8;
    int tlo = lo + tid * sub;
    int thi = tlo + sub; if (thi > hi) thi = hi;
    int s = 0;
    for (int i = tlo; i < thi; ++i) s += g_cnt[i];
    sh[tid] = s;
    __syncthreads();
    // block total via reduction into sbm[0]
    sbm[tid] = sh[tid];
    __syncthreads();
    for (int d = 128; d; d >>= 1) {
        if (tid < d) sbm[tid] += sbm[tid + d];
        __syncthreads();
    }
    if (tid == 0) {
        g_bsum[blockIdx.x] = sbm[0];
        __threadfence();
        atomicAdd(&g_barrier, 1);
        while (atomicAdd(&g_barrier, 0) < gridDim.x) { }
    }
    __syncthreads();

    // phase 2: scan the 256 block sums (redundantly per block)
    int bv = g_bsum[tid];
    sbm[tid] = bv;
    __syncthreads();
    for (int d = 1; d < 256; d <<= 1) {
        int t = (tid >= d) ? sbm[tid - d] : 0;
        __syncthreads();
        sbm[tid] += t;
        __syncthreads();
    }
    if (blockIdx.x == 0 && tid == 0) g_off[n] = sbm[255];
    int block_base = sbm[blockIdx.x] - g_bsum[blockIdx.x];   // exclusive

    // scan per-thread sums within block
    int myv = sh[tid];
    __syncthreads();
    for (int d = 1; d < 256; d <<= 1) {
        int t = (tid >= d) ? sh[tid - d] : 0;
        __syncthreads();
        sh[tid] += t;
        __syncthreads();
    }
    int run = block_base + sh[tid] - myv;
    for (int i = tlo; i < thi; ++i) {
        g_off[i] = run;
        run += g_cnt[i];
    }
}

__global__ void fill_kernel(const int* __restrict__ src, const int* __restrict__ dst,
                            const float* __restrict__ ea, int E) {
    int e = blockIdx.x * blockDim.x + threadIdx.x;
    if (e < E) {
        int p = g_off[dst[e]] + g_rank[e];
        g_epk[p] = make_int2(src[e], __float_as_int(ea[e]));
    }
}

// ---------------------------------------------------------------------------
// Gather: half-warp (16 lanes) per node; uint4 (16B) per lane covers 256B row.
// fp32 accumulation, unroll-4 for MLP, fp16 result store.
// ---------------------------------------------------------------------------
__device__ __forceinline__ void acc_edge4(float* acc, uint4 v, float w) {
    float2 a0 = __half22float2(*reinterpret_cast<__half2*>(&v.x));
    float2 a1 = __half22float2(*reinterpret_cast<__half2*>(&v.y));
    float2 a2 = __half22float2(*reinterpret_cast<__half2*>(&v.z));
    float2 a3 = __half22float2(*reinterpret_cast<__half2*>(&v.w));
    acc[0] = fmaf(w, a0.x, acc[0]); acc[1] = fmaf(w, a0.y, acc[1]);
    acc[2] = fmaf(w, a1.x, acc[2]); acc[3] = fmaf(w, a1.y, acc[3]);
    acc[4] = fmaf(w, a2.x, acc[4]); acc[5] = fmaf(w, a2.y, acc[5]);
    acc[6] = fmaf(w, a3.x, acc[6]); acc[7] = fmaf(w, a3.y, acc[7]);
}

__global__ void gather_kernel(int n) {
    int idx  = blockIdx.x * blockDim.x + threadIdx.x;
    int w    = idx >> 4;
    if (w >= n) return;
    int lane = idx & 15;
    int j   = g_off[w];
    int end = g_off[w + 1];
    const uint4* xb = reinterpret_cast<const uint4*>(g_xh);
    const int2* ep = g_epk;
    float acc[8] = {0.f, 0.f, 0.f, 0.f, 0.f, 0.f, 0.f, 0.f};

    #pragma unroll 1
    for (; j + 4 <= end; j += 4) {
        int2 p0 = ep[j];
        int2 p1 = ep[j + 1];
        int2 p2 = ep[j + 2];
        int2 p3 = ep[j + 3];
        uint4 v0 = __ldg(xb + (size_t)p0.x * 16 + lane);
        uint4 v1 = __ldg(xb + (size_t)p1.x * 16 + lane);
        uint4 v2 = __ldg(xb + (size_t)p2.x * 16 + lane);
        uint4 v3 = __ldg(xb + (size_t)p3.x * 16 + lane);
        acc_edge4(acc, v0, __int_as_float(p0.y));
        acc_edge4(acc, v1, __int_as_float(p1.y));
        acc_edge4(acc, v2, __int_as_float(p2.y));
        acc_edge4(acc, v3, __int_as_float(p3.y));
    }
    #pragma unroll 1
    for (; j < end; ++j) {
        int2 p0 = ep[j];
        uint4 v0 = __ldg(xb + (size_t)p0.x * 16 + lane);
        acc_edge4(acc, v0, __int_as_float(p0.y));
    }

    uint4 o;
    __half2 h;
    h = __float22half2_rn(make_float2(acc[0], acc[1])); o.x = *reinterpret_cast<uint32_t*>(&h);
    h = __float22half2_rn(make_float2(acc[2], acc[3])); o.y = *reinterpret_cast<uint32_t*>(&h);
    h = __float22half2_rn(make_float2(acc[4], acc[5])); o.z = *reinterpret_cast<uint32_t*>(&h);
    h = __float22half2_rn(make_float2(acc[6], acc[7])); o.w = *reinterpret_cast<uint32_t*>(&h);
    reinterpret_cast<uint4*>(g_h)[(size_t)w * 16 + lane] = o;
}

// ---------------------------------------------------------------------------
// HMMA GEMM: out = lrelu((x+h)@W1^T + b1) + lrelu((x*h)@W2^T + b2)
// cp.async double-buffered RAW xh/h tiles; bi-interaction computed on
// ldmatrix fragments (hadd2/hmul2).
// ---------------------------------------------------------------------------
#define SM_W1   0
#define SM_W2   32768
#define SM_TILE 65536          // 2 buffers x (xh 32KB + h 32KB)
#define SM_B1   (SM_TILE + 131072)
#define SM_B2   (SM_B1 + 512)
#define SM_TOT  (SM_B2 + 512)  // 197632 bytes

__device__ __forceinline__ uint32_t swz(int row, int kb) {
    return (uint32_t)(row * 256 + (kb ^ ((row & 7) << 4)));
}

__device__ __forceinline__ uint32_t pack_h2(float a, float b) {
    __half2 h = __float22half2_rn(make_float2(a, b));
    return *reinterpret_cast<uint32_t*>(&h);
}

__device__ __forceinline__ float lrelu(float v) {
    return v >= 0.f ? v : 0.01f * v;
}

__device__ __forceinline__ void ldsm_x4(uint32_t* r, uint32_t addr) {
    asm volatile("ldmatrix.sync.aligned.m8n8.x4.shared.b16 {%0,%1,%2,%3}, [%4];"
                 : "=r"(r[0]), "=r"(r[1]), "=r"(r[2]), "=r"(r[3]) : "r"(addr));
}
__device__ __forceinline__ void ldsm_x2(uint32_t* r, uint32_t addr) {
    asm volatile("ldmatrix.sync.aligned.m8n8.x2.shared.b16 {%0,%1}, [%2];"
                 : "=r"(r[0]), "=r"(r[1]) : "r"(addr));
}
__device__ __forceinline__ void mma16816(float* c, const uint32_t* a, const uint32_t* b) {
    asm volatile(
        "mma.sync.aligned.m16n8k16.row.col.f32.f16.f16.f32 "
        "{%0,%1,%2,%3}, {%4,%5,%6,%7}, {%8,%9}, {%0,%1,%2,%3};"
        : "+f"(c[0]), "+f"(c[1]), "+f"(c[2]), "+f"(c[3])
        : "r"(a[0]), "r"(a[1]), "r"(a[2]), "r"(a[3]), "r"(b[0]), "r"(b[1]));
}

__device__ __forceinline__ uint32_t hadd2u(uint32_t a, uint32_t b) {
    __half2 r = __hadd2(*reinterpret_cast<__half2*>(&a), *reinterpret_cast<__half2*>(&b));
    return *reinterpret_cast<uint32_t*>(&r);
}
__device__ __forceinline__ uint32_t hmul2u(uint32_t a, uint32_t b) {
    __half2 r = __hmul2(*reinterpret_cast<__half2*>(&a), *reinterpret_cast<__half2*>(&b));
    return *reinterpret_cast<uint32_t*>(&r);
}

#define CP16(dst, src) \
    asm volatile("cp.async.cg.shared.global [%0], [%1], 16;" :: "r"(dst), "l"(src))
#define CP_COMMIT() asm volatile("cp.async.commit_group;" ::: "memory")
#define CP_WAIT(N)  asm volatile("cp.async.wait_group %0;" :: "n"(N) : "memory")

__device__ __forceinline__ void stage_tile(uint32_t sb, int buf, int row0,
                                           int n, int tid) {
    uint32_t base_xh = SM_TILE + (uint32_t)buf * 65536;
    uint32_t base_h  = base_xh + 32768;
    #pragma unroll
    for (int it = 0; it < 8; ++it) {
        int i = tid + it * GT;
        int r = i >> 4;
        int c = i & 15;
        int grow = row0 + r;
        if (grow >= n) grow = n - 1;
        uint32_t off = swz(r, c << 4);
        const __half* xs = g_xh + (size_t)grow * D + c * 8;
        const __half* hs = g_h  + (size_t)grow * D + c * 8;
        CP16(sb + base_xh + off, xs);
        CP16(sb + base_h  + off, hs);
    }
}

__global__ __launch_bounds__(GT, 1)
void gemm_kernel(const float* __restrict__ W1, const float* __restrict__ b1,
                 const float* __restrict__ W2, const float* __restrict__ b2,
                 float* __restrict__ out, int n, int ntiles) {
    extern __shared__ char smem[];
    uint32_t sb = (uint32_t)__cvta_generic_to_shared(smem);
    const int tid  = threadIdx.x;
    const int wid  = tid >> 5;
    const int lane = tid & 31;
    const int mbase = (wid >> 1) * 32;
    const int nbase = (wid & 1) * 64;

    for (int i = tid; i < D * D / 8; i += GT) {
        int row = i >> 4;
        int k0  = (i & 15) << 3;
        const float* w1p = W1 + row * D + k0;
        const float* w2p = W2 + row * D + k0;
        float4 a0 = *reinterpret_cast<const float4*>(w1p);
        float4 a1 = *reinterpret_cast<const float4*>(w1p + 4);
        float4 c0 = *reinterpret_cast<const float4*>(w2p);
        float4 c1 = *reinterpret_cast<const float4*>(w2p + 4);
        uint4 u1, u2;
        u1.x = pack_h2(a0.x, a0.y); u1.y = pack_h2(a0.z, a0.w);
        u1.z = pack_h2(a1.x, a1.y); u1.w = pack_h2(a1.z, a1.w);
        u2.x = pack_h2(c0.x, c0.y); u2.y = pack_h2(c0.z, c0.w);
        u2.z = pack_h2(c1.x, c1.y); u2.w = pack_h2(c1.z, c1.w);
        uint32_t off = swz(row, k0 * 2);
        *reinterpret_cast<uint4*>(smem + SM_W1 + off) = u1;
        *reinterpret_cast<uint4*>(smem + SM_W2 + off) = u2;
    }
    if (tid < D) {
        *reinterpret_cast<float*>(smem + SM_B1 + tid * 4) = b1[tid];
        *reinterpret_cast<float*>(smem + SM_B2 + tid * 4) = b2[tid];
    }

    if (blockIdx.x < ntiles) {
        stage_tile(sb, 0, blockIdx.x * TILE_M, n, tid);
    }
    CP_COMMIT();

    int b = 0;
    for (int tile = blockIdx.x; tile < ntiles; tile += gridDim.x) {
        const int row0 = tile * TILE_M;
        const int nxt  = tile + gridDim.x;

        if (nxt < ntiles) {
            stage_tile(sb, b ^ 1, nxt * TILE_M, n, tid);
            CP_COMMIT();
            CP_WAIT(1);
        } else {
            CP_WAIT(0);
        }
        __syncthreads();

        const uint32_t base_xh = SM_TILE + (uint32_t)b * 65536;
        const uint32_t base_h  = base_xh + 32768;

        float c1[2][8][4], c2[2][8][4];
        #pragma unroll
        for (int i = 0; i < 2; ++i)
            #pragma unroll
            for (int j = 0; j < 8; ++j)
                #pragma unroll
                for (int q = 0; q < 4; ++q) { c1[i][j][q] = 0.f; c2[i][j][q] = 0.f; }

        for (int ks = 0; ks < 8; ++ks) {
            const int kb0 = ks * 32;
            uint32_t aA[2][4], aM[2][4];
            #pragma unroll
            for (int i = 0; i < 2; ++i) {
                uint32_t off = swz(mbase + i * 16 + (lane & 15), kb0 + ((lane >> 4) << 4));
                uint32_t xf[4], hf[4];
                ldsm_x4(xf, sb + base_xh + off);
                ldsm_x4(hf, sb + base_h  + off);
                #pragma unroll
                for (int q = 0; q < 4; ++q) {
                    aA[i][q] = hadd2u(xf[q], hf[q]);
                    aM[i][q] = hmul2u(xf[q], hf[q]);
                }
            }
            #pragma unroll
            for (int j = 0; j < 8; ++j) {
                uint32_t boff = swz(nbase + j * 8 + (lane & 7), kb0 + (((lane >> 3) & 1) << 4));
                uint32_t bW1[2], bW2[2];
                ldsm_x2(bW1, sb + SM_W1 + boff);
                ldsm_x2(bW2, sb + SM_W2 + boff);
                #pragma unroll
                for (int i = 0; i < 2; ++i) {
                    mma16816(c1[i][j], aA[i], bW1);
                    mma16816(c2[i][j], aM[i], bW2);
                }
            }
        }

        const int rbase = row0 + mbase + (lane >> 2);
        #pragma unroll
        for (int j = 0; j < 8; ++j) {
            int col = nbase + j * 8 + 2 * (lane & 3);
            float2 bb1 = *reinterpret_cast<const float2*>(smem + SM_B1 + col * 4);
            float2 bb2 = *reinterpret_cast<const float2*>(smem + SM_B2 + col * 4);
            #pragma unroll
            for (int i = 0; i < 2; ++i) {
                int r0 = rbase + i * 16;
                if (r0 < n) {
                    float2 o;
                    o.x = lrelu(c1[i][j][0] + bb1.x) + lrelu(c2[i][j][0] + bb2.x);
                    o.y = lrelu(c1[i][j][1] + bb1.y) + lrelu(c2[i][j][1] + bb2.y);
                    *reinterpret_cast<float2*>(out + (size_t)r0 * D + col) = o;
                }
                int r1 = r0 + 8;
                if (r1 < n) {
                    float2 o;
                    o.x = lrelu(c1[i][j][2] + bb1.x) + lrelu(c2[i][j][2] + bb2.x);
                    o.y = lrelu(c1[i][j][3] + bb1.y) + lrelu(c2[i][j][3] + bb2.y);
                    *reinterpret_cast<float2*>(out + (size_t)r1 * D + col) = o;
                }
            }
        }
        __syncthreads();
        b ^= 1;
    }
}

// ---------------------------------------------------------------------------
// Launch — fork convert_x onto a side stream, overlapped with the CSR chain.
// Inputs: x[N*128] f32, src[E] i32, dst[E] i32, e_attn[E] f32,
//         W1[128*128] f32, b1[128] f32, W2[128*128] f32, b2[128] f32
// ---------------------------------------------------------------------------
extern "C" void kernel_launch(void* const* d_in, const int* in_sizes, int n_in,
                              void* d_out, int out_size) {
    const float* x   = (const float*)d_in[0];
    const int*   src = (const int*)  d_in[1];
    const int*   dst = (const int*)  d_in[2];
    const float* ea  = (const float*)d_in[3];
    const float* W1  = (const float*)d_in[4];
    const float* b1  = (const float*)d_in[5];
    const float* W2  = (const float*)d_in[6];
    const float* b2  = (const float*)d_in[7];
    float*       out = (float*)d_out;

    const int n = in_sizes[0] / D;
    const int E = in_sizes[1];

    cudaStream_t s2;
    cudaEvent_t ef, ec;
    cudaStreamCreateWithFlags(&s2, cudaStreamNonBlocking);
    cudaEventCreateWithFlags(&ef, cudaEventDisableTiming);
    cudaEventCreateWithFlags(&ec, cudaEventDisableTiming);

    // fork: convert x -> fp16 on side stream
    cudaEventRecord(ef, 0);
    cudaStreamWaitEvent(s2, ef, 0);
    convert_x_kernel<<<1024, 256, 0, s2>>>(x, n * D / 8);
    cudaEventRecord(ec, s2);

    // CSR chain on main stream
    zero_cnt_kernel<<<256, 256>>>(n);
    hist_kernel<<<(E + 255) / 256, 256>>>(dst, E);
    scanoff_kernel<<<256, 256>>>(n);
    fill_kernel<<<(E + 255) / 256, 256>>>(src, dst, ea, E);

    // join: gather needs g_xh
    cudaStreamWaitEvent(0, ec, 0);
    gather_kernel<<<(n + 15) / 16, 256>>>(n);

    cudaFuncSetAttribute(gemm_kernel,
                         cudaFuncAttributeMaxDynamicSharedMemorySize, SM_TOT);
    const int ntiles = (n + TILE_M - 1) / TILE_M;
    gemm_kernel<<<148, GT, SM_TOT>>>(W1, b1, W2, b2, out, n, ntiles);

    cudaEventDestroy(ef);
    cudaEventDestroy(ec);
    cudaStreamDestroy(s2);
}